// round 3
// baseline (speedup 1.0000x reference)
#include <cuda_runtime.h>
#include <cuda_bf16.h>
#include <math.h>
#include <limits.h>

#define NN 50000
#define EE 800000
#define MM 3
#define IN_ 256
#define HID_ 16
#define HEADS_ 8
#define HD_ 128
#define OUT_ 8
#define NTASK (MM * NN)
#define CAP 32

typedef unsigned long long ull;

// ---------------- scratch ----------------
__device__ float g_feat[MM * NN * HD_];
__device__ float g_z[MM * NN * HD_];
__device__ float g_el[MM * NN * HEADS_];
__device__ float g_er[MM * NN * HEADS_];
__device__ int   g_deg[NTASK];
__device__ int   g_off[NTASK];
__device__ int   g_cur[NTASK];
__device__ int   g_csr[MM * EE];
__device__ float g_w[MM * NN];
__device__ float g_wsum[MM];
__device__ float g_pz[MM * HD_];

__device__ __forceinline__ void fma2(ull& acc, ull a, ull b) {
    asm("fma.rn.f32x2 %0, %1, %2, %0;" : "+l"(acc) : "l"(a), "l"(b));
}
__device__ __forceinline__ void unpack2(ull v, float& lo, float& hi) {
    asm("mov.b64 {%0,%1}, %2;" : "=f"(lo), "=f"(hi) : "l"(v));
}
__device__ __forceinline__ ull pack2(float lo, float hi) {
    ull d;
    asm("mov.b64 %0, {%1,%2};" : "=l"(d) : "f"(lo), "f"(hi));
    return d;
}
__device__ __forceinline__ float tanh_fast(float x) {
    x = fminf(fmaxf(x, -15.f), 15.f);
    float e = __expf(2.f * x);
    return __fdividef(e - 1.f, e + 1.f);
}

// ---------------- GEMM: feat = h @ fc_w[p], fused el/er epilogue ----------------
// 32 rows x 128 cols tile, f32x2 packed accumulation (column pairs).
__global__ __launch_bounds__(256) void k_gemm(
        const float* __restrict__ h, const float* __restrict__ W,
        const float* __restrict__ al, const float* __restrict__ ar) {
    __shared__ float2 Ad[32][33];   // duplicated (a,a), indexed [k][row]
    __shared__ float4 Bs[32][32];
    int p = blockIdx.y;
    int row0 = blockIdx.x * 32;
    int tid = threadIdx.x;
    int cx = tid & 31;
    int ry = tid >> 5;
    int ry4 = ry * 4;
    const float* Wp = W + (size_t)p * IN_ * HD_;

    ull acc[4][2];
#pragma unroll
    for (int i = 0; i < 4; i++) { acc[i][0] = 0ull; acc[i][1] = 0ull; }

    for (int kk = 0; kk < IN_; kk += 32) {
        {
            int r = tid >> 3;
            int k4 = (tid & 7) * 4;
            float4 av = make_float4(0.f, 0.f, 0.f, 0.f);
            if (row0 + r < NN)
                av = *(const float4*)&h[(size_t)(row0 + r) * IN_ + kk + k4];
            Ad[k4 + 0][r] = make_float2(av.x, av.x);
            Ad[k4 + 1][r] = make_float2(av.y, av.y);
            Ad[k4 + 2][r] = make_float2(av.z, av.z);
            Ad[k4 + 3][r] = make_float2(av.w, av.w);
        }
#pragma unroll
        for (int j = 0; j < 4; j++) {
            int q = tid + 256 * j;
            int bk = q >> 5, bc = q & 31;
            Bs[bk][bc] = *(const float4*)&Wp[(size_t)(kk + bk) * HD_ + bc * 4];
        }
        __syncthreads();
#pragma unroll
        for (int k = 0; k < 32; k++) {
            const ull* bp = (const ull*)&Bs[k][cx];
            ull b01 = bp[0], b23 = bp[1];
            ull a0 = *(const ull*)&Ad[k][ry4 + 0];
            ull a1 = *(const ull*)&Ad[k][ry4 + 1];
            ull a2 = *(const ull*)&Ad[k][ry4 + 2];
            ull a3 = *(const ull*)&Ad[k][ry4 + 3];
            fma2(acc[0][0], a0, b01); fma2(acc[0][1], a0, b23);
            fma2(acc[1][0], a1, b01); fma2(acc[1][1], a1, b23);
            fma2(acc[2][0], a2, b01); fma2(acc[2][1], a2, b23);
            fma2(acc[3][0], a3, b01); fma2(acc[3][1], a3, b23);
        }
        __syncthreads();
    }

    int head = cx >> 2;
    int dbase = (cx * 4) & 15;
    size_t ab = (size_t)p * HEADS_ * HID_ + head * HID_ + dbase;
    float av0 = al[ab + 0], av1 = al[ab + 1], av2 = al[ab + 2], av3 = al[ab + 3];
    float rv0 = ar[ab + 0], rv1 = ar[ab + 1], rv2 = ar[ab + 2], rv3 = ar[ab + 3];

#pragma unroll
    for (int i = 0; i < 4; i++) {
        float c0, c1, c2, c3;
        unpack2(acc[i][0], c0, c1);
        unpack2(acc[i][1], c2, c3);
        int row = row0 + ry4 + i;
        if (row < NN) {
            *(float4*)&g_feat[((size_t)p * NN + row) * HD_ + cx * 4] =
                make_float4(c0, c1, c2, c3);
        }
        float pl = c0 * av0 + c1 * av1 + c2 * av2 + c3 * av3;
        float pr = c0 * rv0 + c1 * rv1 + c2 * rv2 + c3 * rv3;
        pl += __shfl_xor_sync(0xffffffffu, pl, 1);
        pl += __shfl_xor_sync(0xffffffffu, pl, 2);
        pr += __shfl_xor_sync(0xffffffffu, pr, 1);
        pr += __shfl_xor_sync(0xffffffffu, pr, 2);
        if ((cx & 3) == 0 && row < NN) {
            g_el[((size_t)p * NN + row) * HEADS_ + head] = pl;
            g_er[((size_t)p * NN + row) * HEADS_ + head] = pr;
        }
    }
}

// ---------------- CSR build ----------------
__global__ void k_count(const int* __restrict__ edges) {
    int idx = blockIdx.x * blockDim.x + threadIdx.x;
    if (idx >= MM * EE) return;
    int p = idx / EE, e = idx - p * EE;
    int dst = edges[(size_t)p * 2 * EE + EE + e];
    atomicAdd(&g_deg[p * NN + dst], 1);
}

__global__ void k_scan() {
    __shared__ int wsum[32];
    __shared__ int carry_s;
    int tid = threadIdx.x, lane = tid & 31, wid = tid >> 5;
    if (tid == 0) carry_s = 0;
    __syncthreads();
    for (int base = 0; base < NTASK; base += 1024) {
        int i = base + tid;
        int v = (i < NTASK) ? g_deg[i] : 0;
        int x = v;
#pragma unroll
        for (int off = 1; off < 32; off <<= 1) {
            int y = __shfl_up_sync(0xffffffffu, x, off);
            if (lane >= off) x += y;
        }
        if (lane == 31) wsum[wid] = x;
        __syncthreads();
        if (wid == 0) {
            int s = wsum[lane];
#pragma unroll
            for (int off = 1; off < 32; off <<= 1) {
                int y = __shfl_up_sync(0xffffffffu, s, off);
                if (lane >= off) s += y;
            }
            wsum[lane] = s;
        }
        __syncthreads();
        int prefix = carry_s + (wid ? wsum[wid - 1] : 0) + x - v;
        if (i < NTASK) g_off[i] = prefix;
        __syncthreads();
        if (tid == 0) carry_s += wsum[31];
        __syncthreads();
    }
}

__global__ void k_scatter(const int* __restrict__ edges) {
    int idx = blockIdx.x * blockDim.x + threadIdx.x;
    if (idx >= MM * EE) return;
    int p = idx / EE, e = idx - p * EE;
    const int* eb = edges + (size_t)p * 2 * EE;
    int src = eb[e], dst = eb[EE + e];
    int t = p * NN + dst;
    int pos = atomicAdd(&g_cur[t], 1);
    g_csr[g_off[t] + pos] = src;
}

// ---------------- fused edge softmax + aggregation + elu ----------------
__global__ void k_agg() {
    __shared__ float sm_v[8][CAP * 8];
    __shared__ int   sm_src[8][CAP];
    int warp = threadIdx.x >> 5, lane = threadIdx.x & 31;
    int t = blockIdx.x * 8 + warp;
    if (t >= NTASK) return;
    int p = t / NN;
    int deg = g_deg[t];
    int base = g_off[t];

    if (deg == 0) {
        *(float4*)&g_z[(size_t)t * HD_ + lane * 4] = make_float4(0.f, 0.f, 0.f, 0.f);
        return;
    }

    int hA = lane & 7;
    int eSub = lane >> 3;
    int hB = lane >> 2;

    float er_l = 0.f;
    if (lane < 8) er_l = g_er[(size_t)t * HEADS_ + lane];
    float er_hA = __shfl_sync(0xffffffffu, er_l, hA);

    float m = -1e30f, s = 0.f;
    float4 acc = make_float4(0.f, 0.f, 0.f, 0.f);

    for (int c0 = 0; c0 < deg; c0 += CAP) {
        int cn = min(CAP, deg - c0);
        float mc = -1e30f;
        for (int e = eSub; e < cn; e += 4) {
            int src = g_csr[base + c0 + e];
            if (hA == 0) sm_src[warp][e] = src;
            float v = g_el[((size_t)p * NN + src) * HEADS_ + hA] + er_hA;
            v = v > 0.f ? v : 0.2f * v;
            sm_v[warp][e * 8 + hA] = v;
            mc = fmaxf(mc, v);
        }
        mc = fmaxf(mc, __shfl_xor_sync(0xffffffffu, mc, 8));
        mc = fmaxf(mc, __shfl_xor_sync(0xffffffffu, mc, 16));
        float mNew = fmaxf(m, mc);
        float scale = __expf(m - mNew);
        float cs = 0.f;
        for (int e = eSub; e < cn; e += 4) {
            float ex = __expf(sm_v[warp][e * 8 + hA] - mNew);
            sm_v[warp][e * 8 + hA] = ex;
            cs += ex;
        }
        cs += __shfl_xor_sync(0xffffffffu, cs, 8);
        cs += __shfl_xor_sync(0xffffffffu, cs, 16);
        s = s * scale + cs;
        m = mNew;
        float scaleB = __shfl_sync(0xffffffffu, scale, hB);
        acc.x *= scaleB; acc.y *= scaleB; acc.z *= scaleB; acc.w *= scaleB;
        __syncwarp();
#pragma unroll 4
        for (int e = 0; e < cn; e++) {
            int src = sm_src[warp][e];
            float ex = sm_v[warp][e * 8 + hB];
            float4 f = *(const float4*)&g_feat[((size_t)p * NN + src) * HD_ + lane * 4];
            acc.x += ex * f.x; acc.y += ex * f.y; acc.z += ex * f.z; acc.w += ex * f.w;
        }
        __syncwarp();
    }

    float sB = __shfl_sync(0xffffffffu, s, hB);
    float inv = 1.f / sB;
    float zx = acc.x * inv, zy = acc.y * inv, zz = acc.z * inv, zw = acc.w * inv;
    zx = zx > 0.f ? zx : expm1f(zx);
    zy = zy > 0.f ? zy : expm1f(zy);
    zz = zz > 0.f ? zz : expm1f(zz);
    zw = zw > 0.f ? zw : expm1f(zw);
    *(float4*)&g_z[(size_t)t * HD_ + lane * 4] = make_float4(zx, zy, zz, zw);
}

// ---------------- structure attention score: w = tanh(z@W1+b1)@w2 ----------------
__global__ __launch_bounds__(256) void k_w(
        const float* __restrict__ W1, const float* __restrict__ b1,
        const float* __restrict__ w2) {
    __shared__ float2 Ad[32][33];
    __shared__ float4 Bs[32][32];
    int mpath = blockIdx.y;
    int row0 = blockIdx.x * 32;
    int tid = threadIdx.x;
    int cx = tid & 31;
    int ry = tid >> 5;
    int ry4 = ry * 4;

    float4 b1v = *(const float4*)&b1[cx * 4];
    ull acc[4][2];
#pragma unroll
    for (int i = 0; i < 4; i++) {
        acc[i][0] = pack2(b1v.x, b1v.y);
        acc[i][1] = pack2(b1v.z, b1v.w);
    }

    for (int kk = 0; kk < HD_; kk += 32) {
        {
            int r = tid >> 3;
            int k4 = (tid & 7) * 4;
            float4 av = make_float4(0.f, 0.f, 0.f, 0.f);
            if (row0 + r < NN)
                av = *(const float4*)&g_z[((size_t)mpath * NN + row0 + r) * HD_ + kk + k4];
            Ad[k4 + 0][r] = make_float2(av.x, av.x);
            Ad[k4 + 1][r] = make_float2(av.y, av.y);
            Ad[k4 + 2][r] = make_float2(av.z, av.z);
            Ad[k4 + 3][r] = make_float2(av.w, av.w);
        }
#pragma unroll
        for (int j = 0; j < 4; j++) {
            int q = tid + 256 * j;
            int bk = q >> 5, bc = q & 31;
            Bs[bk][bc] = *(const float4*)&W1[(size_t)(kk + bk) * HD_ + bc * 4];
        }
        __syncthreads();
#pragma unroll
        for (int k = 0; k < 32; k++) {
            const ull* bp = (const ull*)&Bs[k][cx];
            ull b01 = bp[0], b23 = bp[1];
            ull a0 = *(const ull*)&Ad[k][ry4 + 0];
            ull a1 = *(const ull*)&Ad[k][ry4 + 1];
            ull a2 = *(const ull*)&Ad[k][ry4 + 2];
            ull a3 = *(const ull*)&Ad[k][ry4 + 3];
            fma2(acc[0][0], a0, b01); fma2(acc[0][1], a0, b23);
            fma2(acc[1][0], a1, b01); fma2(acc[1][1], a1, b23);
            fma2(acc[2][0], a2, b01); fma2(acc[2][1], a2, b23);
            fma2(acc[3][0], a3, b01); fma2(acc[3][1], a3, b23);
        }
        __syncthreads();
    }

    float4 w2v = *(const float4*)&w2[cx * 4];
#pragma unroll
    for (int i = 0; i < 4; i++) {
        float c0, c1, c2, c3;
        unpack2(acc[i][0], c0, c1);
        unpack2(acc[i][1], c2, c3);
        int row = row0 + ry4 + i;
        float tsum = tanh_fast(c0) * w2v.x + tanh_fast(c1) * w2v.y +
                     tanh_fast(c2) * w2v.z + tanh_fast(c3) * w2v.w;
#pragma unroll
        for (int off = 16; off; off >>= 1)
            tsum += __shfl_xor_sync(0xffffffffu, tsum, off);
        if (cx == 0 && row < NN) g_w[(size_t)mpath * NN + row] = tsum;
    }
}

// ---------------- node softmax weighted sum ----------------
#define NODES_PER_BLK 64
__global__ void k_beta() {
    int j = threadIdx.x;
    int n0 = blockIdx.x * NODES_PER_BLK;
    float acc[MM] = {0.f, 0.f, 0.f};
    float wsl[MM] = {0.f, 0.f, 0.f};
    int n1 = n0 + NODES_PER_BLK;
    if (n1 > NN) n1 = NN;
    for (int n = n0; n < n1; n++) {
#pragma unroll
        for (int m = 0; m < MM; m++) {
            float pv = __expf(g_w[(size_t)m * NN + n]);
            acc[m] += pv * g_z[((size_t)m * NN + n) * HD_ + j];
            if (j == 0) wsl[m] += pv;
        }
    }
#pragma unroll
    for (int m = 0; m < MM; m++) {
        atomicAdd(&g_pz[m * HD_ + j], acc[m]);
        if (j == 0) atomicAdd(&g_wsum[m], wsl[m]);
    }
}

__global__ void k_final(const float* __restrict__ pred_w, const float* __restrict__ pred_b,
                        float* __restrict__ out) {
    int t = threadIdx.x;
    if (t < MM * OUT_) {
        int m = t / OUT_, o = t - m * OUT_;
        float inv = 1.f / g_wsum[m];
        float s = pred_b[o];
#pragma unroll 8
        for (int j = 0; j < HD_; j++)
            s += g_pz[m * HD_ + j] * inv * pred_w[(size_t)j * OUT_ + o];
        out[t] = s;
    }
}

// ---------------- launch ----------------
extern "C" void kernel_launch(void* const* d_in, const int* in_sizes, int n_in,
                              void* d_out, int out_size) {
    const float* h      = (const float*)d_in[0];
    const int*   edges  = (const int*)d_in[1];
    const float* fc_w   = (const float*)d_in[2];
    const float* attn_l = (const float*)d_in[3];
    const float* attn_r = (const float*)d_in[4];
    const float* sa_w1  = (const float*)d_in[5];
    const float* sa_b1  = (const float*)d_in[6];
    const float* sa_w2  = (const float*)d_in[7];
    const float* pred_w = (const float*)d_in[8];
    const float* pred_b = (const float*)d_in[9];
    float* out = (float*)d_out;

    void *pdeg, *pcur, *pwsum, *ppz;
    cudaGetSymbolAddress(&pdeg, g_deg);
    cudaGetSymbolAddress(&pcur, g_cur);
    cudaGetSymbolAddress(&pwsum, g_wsum);
    cudaGetSymbolAddress(&ppz, g_pz);
    cudaMemsetAsync(pdeg, 0, sizeof(int) * NTASK);
    cudaMemsetAsync(pcur, 0, sizeof(int) * NTASK);
    cudaMemsetAsync(pwsum, 0, sizeof(float) * MM);
    cudaMemsetAsync(ppz, 0, sizeof(float) * MM * HD_);

    dim3 gg((NN + 31) / 32, MM);
    k_gemm<<<gg, 256>>>(h, fc_w, attn_l, attn_r);

    int et = MM * EE;
    k_count<<<(et + 255) / 256, 256>>>(edges);
    k_scan<<<1, 1024>>>();
    k_scatter<<<(et + 255) / 256, 256>>>(edges);

    k_agg<<<(NTASK + 7) / 8, 256>>>();

    dim3 gw((NN + 31) / 32, MM);
    k_w<<<gw, 256>>>(sa_w1, sa_b1, sa_w2);
    k_beta<<<(NN + NODES_PER_BLK - 1) / NODES_PER_BLK, 128>>>();
    k_final<<<1, 32>>>(pred_w, pred_b, out);
}

// round 4
// speedup vs baseline: 1.5901x; 1.5901x over previous
#include <cuda_runtime.h>
#include <cuda_bf16.h>
#include <math.h>
#include <limits.h>

#define NN 50000
#define EE 800000
#define MM 3
#define IN_ 256
#define HID_ 16
#define HEADS_ 8
#define HD_ 128
#define OUT_ 8
#define NTASK (MM * NN)
#define CAP 32

// ---------------- scratch ----------------
__device__ float g_feat[MM * NN * HD_];
__device__ float g_z[MM * NN * HD_];
__device__ float g_el[MM * NN * HEADS_];
__device__ float g_er[MM * NN * HEADS_];
__device__ int   g_deg[NTASK];
__device__ int   g_off[NTASK];
__device__ int   g_cur[NTASK];
__device__ int   g_csr[MM * EE];
__device__ float g_w[MM * NN];
__device__ float g_wsum[MM];
__device__ float g_pz[MM * HD_];

__device__ __forceinline__ unsigned cvt_tf32(float x) {
    unsigned r;
    asm("cvt.rna.tf32.f32 %0, %1;" : "=r"(r) : "f"(x));
    return r;
}
__device__ __forceinline__ void mma_tf32(float* c, const unsigned* a,
                                         unsigned b0, unsigned b1) {
    asm("mma.sync.aligned.m16n8k8.row.col.f32.tf32.tf32.f32 "
        "{%0,%1,%2,%3},{%4,%5,%6,%7},{%8,%9},{%0,%1,%2,%3};"
        : "+f"(c[0]), "+f"(c[1]), "+f"(c[2]), "+f"(c[3])
        : "r"(a[0]), "r"(a[1]), "r"(a[2]), "r"(a[3]), "r"(b0), "r"(b1));
}
__device__ __forceinline__ float tanh_fast(float x) {
    x = fminf(fmaxf(x, -15.f), 15.f);
    float e = __expf(2.f * x);
    return __fdividef(e - 1.f, e + 1.f);
}

// ---------------- GEMM: feat = h @ fc_w[p] (tf32 mma), fused el/er ----------------
// block tile 128x128, 8 warps (4M x 2N), warp tile 32x64.
__global__ __launch_bounds__(256) void k_gemm(
        const float* __restrict__ h, const float* __restrict__ W,
        const float* __restrict__ al, const float* __restrict__ ar) {
    __shared__ float As[128][33];
    __shared__ float Bs[32][132];
    int p = blockIdx.y;
    int row0 = blockIdx.x * 128;
    int tid = threadIdx.x;
    int w = tid >> 5, t = tid & 31;
    int mrow = (w & 3) * 32;
    int ncol = (w >> 2) * 64;
    const float* Wp = W + (size_t)p * IN_ * HD_;

    float acc[2][8][4];
#pragma unroll
    for (int mf = 0; mf < 2; mf++)
#pragma unroll
        for (int nf = 0; nf < 8; nf++)
#pragma unroll
            for (int k = 0; k < 4; k++) acc[mf][nf][k] = 0.f;

    for (int kk = 0; kk < IN_; kk += 32) {
#pragma unroll
        for (int j = 0; j < 4; j++) {
            int idx = tid + 256 * j;
            int r = idx >> 3;
            int c = (idx & 7) * 4;
            float4 v = make_float4(0.f, 0.f, 0.f, 0.f);
            if (row0 + r < NN)
                v = *(const float4*)&h[(size_t)(row0 + r) * IN_ + kk + c];
            As[r][c] = v.x; As[r][c + 1] = v.y; As[r][c + 2] = v.z; As[r][c + 3] = v.w;
        }
#pragma unroll
        for (int j = 0; j < 4; j++) {
            int idx = tid + 256 * j;
            int r = idx >> 5;
            int c = (idx & 31) * 4;
            float4 v = *(const float4*)&Wp[(size_t)(kk + r) * HD_ + c];
            Bs[r][c] = v.x; Bs[r][c + 1] = v.y; Bs[r][c + 2] = v.z; Bs[r][c + 3] = v.w;
        }
        __syncthreads();
#pragma unroll
        for (int ks = 0; ks < 32; ks += 8) {
            unsigned a[2][4];
#pragma unroll
            for (int mf = 0; mf < 2; mf++) {
                int r = mrow + mf * 16 + (t >> 2);
                int kc = ks + (t & 3);
                a[mf][0] = cvt_tf32(As[r][kc]);
                a[mf][1] = cvt_tf32(As[r + 8][kc]);
                a[mf][2] = cvt_tf32(As[r][kc + 4]);
                a[mf][3] = cvt_tf32(As[r + 8][kc + 4]);
            }
#pragma unroll
            for (int nf = 0; nf < 8; nf++) {
                int col = ncol + nf * 8 + (t >> 2);
                int kc = ks + (t & 3);
                unsigned b0 = cvt_tf32(Bs[kc][col]);
                unsigned b1 = cvt_tf32(Bs[kc + 4][col]);
                mma_tf32(acc[0][nf], a[0], b0, b1);
                mma_tf32(acc[1][nf], a[1], b0, b1);
            }
        }
        __syncthreads();
    }

    int headbase = (w >> 2) * 4;
    size_t pn = (size_t)p * NN;
#pragma unroll
    for (int mf = 0; mf < 2; mf++) {
        int ra = row0 + mrow + mf * 16 + (t >> 2);
        int rb = ra + 8;
#pragma unroll
        for (int nf = 0; nf < 8; nf++) {
            int col = ncol + nf * 8 + (t & 3) * 2;
            if (ra < NN)
                *(float2*)&g_feat[(pn + ra) * HD_ + col] =
                    make_float2(acc[mf][nf][0], acc[mf][nf][1]);
            if (rb < NN)
                *(float2*)&g_feat[(pn + rb) * HD_ + col] =
                    make_float2(acc[mf][nf][2], acc[mf][nf][3]);
        }
#pragma unroll
        for (int hh = 0; hh < 4; hh++) {
            float sAl = 0.f, sBl = 0.f, sAr = 0.f, sBr = 0.f;
#pragma unroll
            for (int q = 0; q < 2; q++) {
                int nf = hh * 2 + q;
                int col = ncol + nf * 8 + (t & 3) * 2;
                float al0 = al[(size_t)p * HD_ + col], al1 = al[(size_t)p * HD_ + col + 1];
                float ar0 = ar[(size_t)p * HD_ + col], ar1 = ar[(size_t)p * HD_ + col + 1];
                sAl += acc[mf][nf][0] * al0 + acc[mf][nf][1] * al1;
                sBl += acc[mf][nf][2] * al0 + acc[mf][nf][3] * al1;
                sAr += acc[mf][nf][0] * ar0 + acc[mf][nf][1] * ar1;
                sBr += acc[mf][nf][2] * ar0 + acc[mf][nf][3] * ar1;
            }
            sAl += __shfl_xor_sync(0xffffffffu, sAl, 1);
            sAl += __shfl_xor_sync(0xffffffffu, sAl, 2);
            sBl += __shfl_xor_sync(0xffffffffu, sBl, 1);
            sBl += __shfl_xor_sync(0xffffffffu, sBl, 2);
            sAr += __shfl_xor_sync(0xffffffffu, sAr, 1);
            sAr += __shfl_xor_sync(0xffffffffu, sAr, 2);
            sBr += __shfl_xor_sync(0xffffffffu, sBr, 1);
            sBr += __shfl_xor_sync(0xffffffffu, sBr, 2);
            if ((t & 3) == 0) {
                if (ra < NN) {
                    g_el[(pn + ra) * HEADS_ + headbase + hh] = sAl;
                    g_er[(pn + ra) * HEADS_ + headbase + hh] = sAr;
                }
                if (rb < NN) {
                    g_el[(pn + rb) * HEADS_ + headbase + hh] = sBl;
                    g_er[(pn + rb) * HEADS_ + headbase + hh] = sBr;
                }
            }
        }
    }
}

// ---------------- CSR build ----------------
__global__ void k_count(const int* __restrict__ edges) {
    int idx = blockIdx.x * blockDim.x + threadIdx.x;
    if (idx >= MM * EE) return;
    int p = idx / EE, e = idx - p * EE;
    int dst = edges[(size_t)p * 2 * EE + EE + e];
    atomicAdd(&g_deg[p * NN + dst], 1);
}

__global__ void k_scan() {
    __shared__ int wsum[32];
    __shared__ int carry_s;
    int tid = threadIdx.x, lane = tid & 31, wid = tid >> 5;
    if (tid == 0) carry_s = 0;
    __syncthreads();
    for (int base = 0; base < NTASK; base += 1024) {
        int i = base + tid;
        int v = (i < NTASK) ? g_deg[i] : 0;
        int x = v;
#pragma unroll
        for (int off = 1; off < 32; off <<= 1) {
            int y = __shfl_up_sync(0xffffffffu, x, off);
            if (lane >= off) x += y;
        }
        if (lane == 31) wsum[wid] = x;
        __syncthreads();
        if (wid == 0) {
            int s = wsum[lane];
#pragma unroll
            for (int off = 1; off < 32; off <<= 1) {
                int y = __shfl_up_sync(0xffffffffu, s, off);
                if (lane >= off) s += y;
            }
            wsum[lane] = s;
        }
        __syncthreads();
        int prefix = carry_s + (wid ? wsum[wid - 1] : 0) + x - v;
        if (i < NTASK) g_off[i] = prefix;
        __syncthreads();
        if (tid == 0) carry_s += wsum[31];
        __syncthreads();
    }
}

__global__ void k_scatter(const int* __restrict__ edges) {
    int idx = blockIdx.x * blockDim.x + threadIdx.x;
    if (idx >= MM * EE) return;
    int p = idx / EE, e = idx - p * EE;
    const int* eb = edges + (size_t)p * 2 * EE;
    int src = eb[e], dst = eb[EE + e];
    int t = p * NN + dst;
    int pos = atomicAdd(&g_cur[t], 1);
    g_csr[g_off[t] + pos] = src;
}

// ---------------- fused edge softmax + aggregation + elu ----------------
__global__ void k_agg() {
    __shared__ float sm_v[8][CAP * 8];
    __shared__ int   sm_src[8][CAP];
    int warp = threadIdx.x >> 5, lane = threadIdx.x & 31;
    int t = blockIdx.x * 8 + warp;
    if (t >= NTASK) return;
    int p = t / NN;
    int deg = g_deg[t];
    int base = g_off[t];

    if (deg == 0) {
        *(float4*)&g_z[(size_t)t * HD_ + lane * 4] = make_float4(0.f, 0.f, 0.f, 0.f);
        return;
    }

    int hA = lane & 7;
    int eSub = lane >> 3;
    int hB = lane >> 2;

    float er_l = 0.f;
    if (lane < 8) er_l = g_er[(size_t)t * HEADS_ + lane];
    float er_hA = __shfl_sync(0xffffffffu, er_l, hA);

    float m = -1e30f, s = 0.f;
    float4 acc = make_float4(0.f, 0.f, 0.f, 0.f);

    for (int c0 = 0; c0 < deg; c0 += CAP) {
        int cn = min(CAP, deg - c0);
        float mc = -1e30f;
        for (int e = eSub; e < cn; e += 4) {
            int src = g_csr[base + c0 + e];
            if (hA == 0) sm_src[warp][e] = src;
            float v = g_el[((size_t)p * NN + src) * HEADS_ + hA] + er_hA;
            v = v > 0.f ? v : 0.2f * v;
            sm_v[warp][e * 8 + hA] = v;
            mc = fmaxf(mc, v);
        }
        mc = fmaxf(mc, __shfl_xor_sync(0xffffffffu, mc, 8));
        mc = fmaxf(mc, __shfl_xor_sync(0xffffffffu, mc, 16));
        float mNew = fmaxf(m, mc);
        float scale = __expf(m - mNew);
        float cs = 0.f;
        for (int e = eSub; e < cn; e += 4) {
            float ex = __expf(sm_v[warp][e * 8 + hA] - mNew);
            sm_v[warp][e * 8 + hA] = ex;
            cs += ex;
        }
        cs += __shfl_xor_sync(0xffffffffu, cs, 8);
        cs += __shfl_xor_sync(0xffffffffu, cs, 16);
        s = s * scale + cs;
        m = mNew;
        float scaleB = __shfl_sync(0xffffffffu, scale, hB);
        acc.x *= scaleB; acc.y *= scaleB; acc.z *= scaleB; acc.w *= scaleB;
        __syncwarp();
#pragma unroll 4
        for (int e = 0; e < cn; e++) {
            int src = sm_src[warp][e];
            float ex = sm_v[warp][e * 8 + hB];
            float4 f = *(const float4*)&g_feat[((size_t)p * NN + src) * HD_ + lane * 4];
            acc.x += ex * f.x; acc.y += ex * f.y; acc.z += ex * f.z; acc.w += ex * f.w;
        }
        __syncwarp();
    }

    float sB = __shfl_sync(0xffffffffu, s, hB);
    float inv = 1.f / sB;
    float zx = acc.x * inv, zy = acc.y * inv, zz = acc.z * inv, zw = acc.w * inv;
    zx = zx > 0.f ? zx : expm1f(zx);
    zy = zy > 0.f ? zy : expm1f(zy);
    zz = zz > 0.f ? zz : expm1f(zz);
    zw = zw > 0.f ? zw : expm1f(zw);
    *(float4*)&g_z[(size_t)t * HD_ + lane * 4] = make_float4(zx, zy, zz, zw);
}

// ---------------- structure attention: w = tanh(z@W1+b1)@w2 (tf32 mma) ----------------
__global__ __launch_bounds__(256) void k_w(
        const float* __restrict__ W1, const float* __restrict__ b1,
        const float* __restrict__ w2) {
    __shared__ float As[128][33];
    __shared__ float Bs[32][132];
    int mpath = blockIdx.y;
    int row0 = blockIdx.x * 128;
    int tid = threadIdx.x;
    int w = tid >> 5, t = tid & 31;
    int mrow = (w & 3) * 32;
    int ncol = (w >> 2) * 64;

    float acc[2][8][4];
#pragma unroll
    for (int nf = 0; nf < 8; nf++) {
        int col = ncol + nf * 8 + (t & 3) * 2;
        float b0 = b1[col], b1v = b1[col + 1];
#pragma unroll
        for (int mf = 0; mf < 2; mf++) {
            acc[mf][nf][0] = b0; acc[mf][nf][1] = b1v;
            acc[mf][nf][2] = b0; acc[mf][nf][3] = b1v;
        }
    }

    for (int kk = 0; kk < HD_; kk += 32) {
#pragma unroll
        for (int j = 0; j < 4; j++) {
            int idx = tid + 256 * j;
            int r = idx >> 3;
            int c = (idx & 7) * 4;
            float4 v = make_float4(0.f, 0.f, 0.f, 0.f);
            if (row0 + r < NN)
                v = *(const float4*)&g_z[((size_t)mpath * NN + row0 + r) * HD_ + kk + c];
            As[r][c] = v.x; As[r][c + 1] = v.y; As[r][c + 2] = v.z; As[r][c + 3] = v.w;
        }
#pragma unroll
        for (int j = 0; j < 4; j++) {
            int idx = tid + 256 * j;
            int r = idx >> 5;
            int c = (idx & 31) * 4;
            float4 v = *(const float4*)&W1[(size_t)(kk + r) * HD_ + c];
            Bs[r][c] = v.x; Bs[r][c + 1] = v.y; Bs[r][c + 2] = v.z; Bs[r][c + 3] = v.w;
        }
        __syncthreads();
#pragma unroll
        for (int ks = 0; ks < 32; ks += 8) {
            unsigned a[2][4];
#pragma unroll
            for (int mf = 0; mf < 2; mf++) {
                int r = mrow + mf * 16 + (t >> 2);
                int kc = ks + (t & 3);
                a[mf][0] = cvt_tf32(As[r][kc]);
                a[mf][1] = cvt_tf32(As[r + 8][kc]);
                a[mf][2] = cvt_tf32(As[r][kc + 4]);
                a[mf][3] = cvt_tf32(As[r + 8][kc + 4]);
            }
#pragma unroll
            for (int nf = 0; nf < 8; nf++) {
                int col = ncol + nf * 8 + (t >> 2);
                int kc = ks + (t & 3);
                unsigned b0 = cvt_tf32(Bs[kc][col]);
                unsigned b1f = cvt_tf32(Bs[kc + 4][col]);
                mma_tf32(acc[0][nf], a[0], b0, b1f);
                mma_tf32(acc[1][nf], a[1], b0, b1f);
            }
        }
        __syncthreads();
    }

#pragma unroll
    for (int mf = 0; mf < 2; mf++) {
        int ra = row0 + mrow + mf * 16 + (t >> 2);
        int rb = ra + 8;
        float tA = 0.f, tB = 0.f;
#pragma unroll
        for (int nf = 0; nf < 8; nf++) {
            int col = ncol + nf * 8 + (t & 3) * 2;
            float w0 = w2[col], w1v = w2[col + 1];
            tA += tanh_fast(acc[mf][nf][0]) * w0 + tanh_fast(acc[mf][nf][1]) * w1v;
            tB += tanh_fast(acc[mf][nf][2]) * w0 + tanh_fast(acc[mf][nf][3]) * w1v;
        }
        tA += __shfl_xor_sync(0xffffffffu, tA, 1);
        tA += __shfl_xor_sync(0xffffffffu, tA, 2);
        tB += __shfl_xor_sync(0xffffffffu, tB, 1);
        tB += __shfl_xor_sync(0xffffffffu, tB, 2);
        if ((t & 3) == 0) {
            if (ra < NN) atomicAdd(&g_w[(size_t)mpath * NN + ra], tA);
            if (rb < NN) atomicAdd(&g_w[(size_t)mpath * NN + rb], tB);
        }
    }
}

// ---------------- node softmax weighted sum ----------------
#define NODES_PER_BLK 64
__global__ void k_beta() {
    int j = threadIdx.x;
    int n0 = blockIdx.x * NODES_PER_BLK;
    float acc[MM] = {0.f, 0.f, 0.f};
    float wsl[MM] = {0.f, 0.f, 0.f};
    int n1 = n0 + NODES_PER_BLK;
    if (n1 > NN) n1 = NN;
    for (int n = n0; n < n1; n++) {
#pragma unroll
        for (int m = 0; m < MM; m++) {
            float pv = __expf(g_w[(size_t)m * NN + n]);
            acc[m] += pv * g_z[((size_t)m * NN + n) * HD_ + j];
            if (j == 0) wsl[m] += pv;
        }
    }
#pragma unroll
    for (int m = 0; m < MM; m++) {
        atomicAdd(&g_pz[m * HD_ + j], acc[m]);
        if (j == 0) atomicAdd(&g_wsum[m], wsl[m]);
    }
}

__global__ void k_final(const float* __restrict__ pred_w, const float* __restrict__ pred_b,
                        float* __restrict__ out) {
    int t = threadIdx.x;
    if (t < MM * OUT_) {
        int m = t / OUT_, o = t - m * OUT_;
        float inv = 1.f / g_wsum[m];
        float s = pred_b[o];
#pragma unroll 8
        for (int j = 0; j < HD_; j++)
            s += g_pz[m * HD_ + j] * inv * pred_w[(size_t)j * OUT_ + o];
        out[t] = s;
    }
}

// ---------------- launch ----------------
extern "C" void kernel_launch(void* const* d_in, const int* in_sizes, int n_in,
                              void* d_out, int out_size) {
    const float* h      = (const float*)d_in[0];
    const int*   edges  = (const int*)d_in[1];
    const float* fc_w   = (const float*)d_in[2];
    const float* attn_l = (const float*)d_in[3];
    const float* attn_r = (const float*)d_in[4];
    const float* sa_w1  = (const float*)d_in[5];
    const float* sa_b1  = (const float*)d_in[6];
    const float* sa_w2  = (const float*)d_in[7];
    const float* pred_w = (const float*)d_in[8];
    const float* pred_b = (const float*)d_in[9];
    float* out = (float*)d_out;

    void *pdeg, *pcur, *pwsum, *ppz, *pw;
    cudaGetSymbolAddress(&pdeg, g_deg);
    cudaGetSymbolAddress(&pcur, g_cur);
    cudaGetSymbolAddress(&pwsum, g_wsum);
    cudaGetSymbolAddress(&ppz, g_pz);
    cudaGetSymbolAddress(&pw, g_w);
    cudaMemsetAsync(pdeg, 0, sizeof(int) * NTASK);
    cudaMemsetAsync(pcur, 0, sizeof(int) * NTASK);
    cudaMemsetAsync(pwsum, 0, sizeof(float) * MM);
    cudaMemsetAsync(ppz, 0, sizeof(float) * MM * HD_);
    cudaMemsetAsync(pw, 0, sizeof(float) * MM * NN);

    dim3 gg((NN + 127) / 128, MM);
    k_gemm<<<gg, 256>>>(h, fc_w, attn_l, attn_r);

    int et = MM * EE;
    k_count<<<(et + 255) / 256, 256>>>(edges);
    k_scan<<<1, 1024>>>();
    k_scatter<<<(et + 255) / 256, 256>>>(edges);

    k_agg<<<(NTASK + 7) / 8, 256>>>();

    k_w<<<gg, 256>>>(sa_w1, sa_b1, sa_w2);
    k_beta<<<(NN + NODES_PER_BLK - 1) / NODES_PER_BLK, 128>>>();
    k_final<<<1, 32>>>(pred_w, pred_b, out);
}

// round 6
// speedup vs baseline: 1.5994x; 1.0059x over previous
#include <cuda_runtime.h>
#include <cuda_bf16.h>
#include <math.h>
#include <limits.h>

#define NN 50000
#define EE 800000
#define MM 3
#define IN_ 256
#define HID_ 16
#define HEADS_ 8
#define HD_ 128
#define OUT_ 8
#define NTASK (MM * NN)
#define CAP 32

// ---------------- scratch ----------------
__device__ float g_feat[MM * NN * HD_];
__device__ float g_z[MM * NN * HD_];
__device__ float g_el[MM * NN * HEADS_];
__device__ float g_er[MM * NN * HEADS_];
__device__ int   g_deg[NTASK];
__device__ int   g_off[NTASK];
__device__ int   g_cur[NTASK];
__device__ int   g_csr[MM * EE];
__device__ float g_w[MM * NN];
__device__ float g_wsum[MM];
__device__ float g_pz[MM * HD_];

__device__ __forceinline__ unsigned cvt_tf32(float x) {
    unsigned r;
    asm("cvt.rna.tf32.f32 %0, %1;" : "=r"(r) : "f"(x));
    return r;
}
__device__ __forceinline__ void mma_tf32(float* c, const unsigned* a,
                                         unsigned b0, unsigned b1) {
    asm("mma.sync.aligned.m16n8k8.row.col.f32.tf32.tf32.f32 "
        "{%0,%1,%2,%3},{%4,%5,%6,%7},{%8,%9},{%0,%1,%2,%3};"
        : "+f"(c[0]), "+f"(c[1]), "+f"(c[2]), "+f"(c[3])
        : "r"(a[0]), "r"(a[1]), "r"(a[2]), "r"(a[3]), "r"(b0), "r"(b1));
}
__device__ __forceinline__ float tanh_fast(float x) {
    x = fminf(fmaxf(x, -15.f), 15.f);
    float e = __expf(2.f * x);
    return __fdividef(e - 1.f, e + 1.f);
}

// ---------------- GEMM: feat = h @ fc_w[p] (tf32 mma), fused el/er ----------------
// block tile 128x128, 8 warps (4M x 2N). tf32 conversion done at smem-store time.
__global__ __launch_bounds__(256) void k_gemm(
        const float* __restrict__ h, const float* __restrict__ W,
        const float* __restrict__ al, const float* __restrict__ ar) {
    __shared__ unsigned As[128][33];
    __shared__ unsigned Bs[32][132];
    int p = blockIdx.y;
    int row0 = blockIdx.x * 128;
    int tid = threadIdx.x;
    int w = tid >> 5, t = tid & 31;
    int mrow = (w & 3) * 32;
    int ncol = (w >> 2) * 64;
    const float* Wp = W + (size_t)p * IN_ * HD_;

    float acc[2][8][4];
#pragma unroll
    for (int mf = 0; mf < 2; mf++)
#pragma unroll
        for (int nf = 0; nf < 8; nf++)
#pragma unroll
            for (int k = 0; k < 4; k++) acc[mf][nf][k] = 0.f;

    for (int kk = 0; kk < IN_; kk += 32) {
#pragma unroll
        for (int j = 0; j < 4; j++) {
            int idx = tid + 256 * j;
            int r = idx >> 3;
            int c = (idx & 7) * 4;
            float4 v = make_float4(0.f, 0.f, 0.f, 0.f);
            if (row0 + r < NN)
                v = *(const float4*)&h[(size_t)(row0 + r) * IN_ + kk + c];
            As[r][c] = cvt_tf32(v.x); As[r][c + 1] = cvt_tf32(v.y);
            As[r][c + 2] = cvt_tf32(v.z); As[r][c + 3] = cvt_tf32(v.w);
        }
#pragma unroll
        for (int j = 0; j < 4; j++) {
            int idx = tid + 256 * j;
            int r = idx >> 5;
            int c = (idx & 31) * 4;
            float4 v = *(const float4*)&Wp[(size_t)(kk + r) * HD_ + c];
            Bs[r][c] = cvt_tf32(v.x); Bs[r][c + 1] = cvt_tf32(v.y);
            Bs[r][c + 2] = cvt_tf32(v.z); Bs[r][c + 3] = cvt_tf32(v.w);
        }
        __syncthreads();
#pragma unroll
        for (int ks = 0; ks < 32; ks += 8) {
            unsigned a[2][4];
#pragma unroll
            for (int mf = 0; mf < 2; mf++) {
                int r = mrow + mf * 16 + (t >> 2);
                int kc = ks + (t & 3);
                a[mf][0] = As[r][kc];
                a[mf][1] = As[r + 8][kc];
                a[mf][2] = As[r][kc + 4];
                a[mf][3] = As[r + 8][kc + 4];
            }
#pragma unroll
            for (int nf = 0; nf < 8; nf++) {
                int col = ncol + nf * 8 + (t >> 2);
                int kc = ks + (t & 3);
                unsigned b0 = Bs[kc][col];
                unsigned b1 = Bs[kc + 4][col];
                mma_tf32(acc[0][nf], a[0], b0, b1);
                mma_tf32(acc[1][nf], a[1], b0, b1);
            }
        }
        __syncthreads();
    }

    int headbase = (w >> 2) * 4;
    size_t pn = (size_t)p * NN;
#pragma unroll
    for (int mf = 0; mf < 2; mf++) {
        int ra = row0 + mrow + mf * 16 + (t >> 2);
        int rb = ra + 8;
#pragma unroll
        for (int nf = 0; nf < 8; nf++) {
            int col = ncol + nf * 8 + (t & 3) * 2;
            if (ra < NN)
                *(float2*)&g_feat[(pn + ra) * HD_ + col] =
                    make_float2(acc[mf][nf][0], acc[mf][nf][1]);
            if (rb < NN)
                *(float2*)&g_feat[(pn + rb) * HD_ + col] =
                    make_float2(acc[mf][nf][2], acc[mf][nf][3]);
        }
#pragma unroll
        for (int hh = 0; hh < 4; hh++) {
            float sAl = 0.f, sBl = 0.f, sAr = 0.f, sBr = 0.f;
#pragma unroll
            for (int q = 0; q < 2; q++) {
                int nf = hh * 2 + q;
                int col = ncol + nf * 8 + (t & 3) * 2;
                float al0 = al[(size_t)p * HD_ + col], al1 = al[(size_t)p * HD_ + col + 1];
                float ar0 = ar[(size_t)p * HD_ + col], ar1 = ar[(size_t)p * HD_ + col + 1];
                sAl += acc[mf][nf][0] * al0 + acc[mf][nf][1] * al1;
                sBl += acc[mf][nf][2] * al0 + acc[mf][nf][3] * al1;
                sAr += acc[mf][nf][0] * ar0 + acc[mf][nf][1] * ar1;
                sBr += acc[mf][nf][2] * ar0 + acc[mf][nf][3] * ar1;
            }
            sAl += __shfl_xor_sync(0xffffffffu, sAl, 1);
            sAl += __shfl_xor_sync(0xffffffffu, sAl, 2);
            sBl += __shfl_xor_sync(0xffffffffu, sBl, 1);
            sBl += __shfl_xor_sync(0xffffffffu, sBl, 2);
            sAr += __shfl_xor_sync(0xffffffffu, sAr, 1);
            sAr += __shfl_xor_sync(0xffffffffu, sAr, 2);
            sBr += __shfl_xor_sync(0xffffffffu, sBr, 1);
            sBr += __shfl_xor_sync(0xffffffffu, sBr, 2);
            if ((t & 3) == 0) {
                if (ra < NN) {
                    g_el[(pn + ra) * HEADS_ + headbase + hh] = sAl;
                    g_er[(pn + ra) * HEADS_ + headbase + hh] = sAr;
                }
                if (rb < NN) {
                    g_el[(pn + rb) * HEADS_ + headbase + hh] = sBl;
                    g_er[(pn + rb) * HEADS_ + headbase + hh] = sBr;
                }
            }
        }
    }
}

// ---------------- CSR build ----------------
__global__ void k_count(const int* __restrict__ edges) {
    int idx = blockIdx.x * blockDim.x + threadIdx.x;
    if (idx >= MM * EE) return;
    int p = idx / EE, e = idx - p * EE;
    int dst = edges[(size_t)p * 2 * EE + EE + e];
    atomicAdd(&g_deg[p * NN + dst], 1);
}

__global__ void k_scan() {
    __shared__ int wsum[32];
    __shared__ int carry_s;
    int tid = threadIdx.x, lane = tid & 31, wid = tid >> 5;
    if (tid == 0) carry_s = 0;
    __syncthreads();
    for (int base = 0; base < NTASK; base += 1024) {
        int i = base + tid;
        int v = (i < NTASK) ? g_deg[i] : 0;
        int x = v;
#pragma unroll
        for (int off = 1; off < 32; off <<= 1) {
            int y = __shfl_up_sync(0xffffffffu, x, off);
            if (lane >= off) x += y;
        }
        if (lane == 31) wsum[wid] = x;
        __syncthreads();
        if (wid == 0) {
            int s = wsum[lane];
#pragma unroll
            for (int off = 1; off < 32; off <<= 1) {
                int y = __shfl_up_sync(0xffffffffu, s, off);
                if (lane >= off) s += y;
            }
            wsum[lane] = s;
        }
        __syncthreads();
        int prefix = carry_s + (wid ? wsum[wid - 1] : 0) + x - v;
        if (i < NTASK) g_off[i] = prefix;
        __syncthreads();
        if (tid == 0) carry_s += wsum[31];
        __syncthreads();
    }
}

// g_cur pre-initialized to g_off (memcpy D2D); pos is absolute
__global__ void k_scatter(const int* __restrict__ edges) {
    int idx = blockIdx.x * blockDim.x + threadIdx.x;
    if (idx >= MM * EE) return;
    int p = idx / EE, e = idx - p * EE;
    const int* eb = edges + (size_t)p * 2 * EE;
    int src = eb[e], dst = eb[EE + e];
    int pos = atomicAdd(&g_cur[p * NN + dst], 1);
    g_csr[pos] = src;
}

// ---------------- fused edge softmax + aggregation + elu (no-max softmax) ----------------
__global__ void k_agg() {
    __shared__ float sm_v[8][CAP * 8];
    __shared__ int   sm_src[8][CAP];
    int warp = threadIdx.x >> 5, lane = threadIdx.x & 31;
    int t = blockIdx.x * 8 + warp;
    if (t >= NTASK) return;
    int p = t / NN;
    int deg = g_deg[t];
    int base = g_off[t];

    if (deg == 0) {
        *(float4*)&g_z[(size_t)t * HD_ + lane * 4] = make_float4(0.f, 0.f, 0.f, 0.f);
        return;
    }

    int hA = lane & 7;
    int eSub = lane >> 3;
    int hB = lane >> 2;

    float er_l = 0.f;
    if (lane < 8) er_l = g_er[(size_t)t * HEADS_ + lane];
    float er_hA = __shfl_sync(0xffffffffu, er_l, hA);

    float s = 0.f;
    float4 acc = make_float4(0.f, 0.f, 0.f, 0.f);

    for (int c0 = 0; c0 < deg; c0 += CAP) {
        int cn = min(CAP, deg - c0);
        float cs = 0.f;
        for (int e = eSub; e < cn; e += 4) {
            int src = g_csr[base + c0 + e];
            if (hA == 0) sm_src[warp][e] = src;
            float v = g_el[((size_t)p * NN + src) * HEADS_ + hA] + er_hA;
            v = v > 0.f ? v : 0.2f * v;
            float ex = __expf(v);
            sm_v[warp][e * 8 + hA] = ex;
            cs += ex;
        }
        cs += __shfl_xor_sync(0xffffffffu, cs, 8);
        cs += __shfl_xor_sync(0xffffffffu, cs, 16);
        s += cs;
        __syncwarp();
#pragma unroll 4
        for (int e = 0; e < cn; e++) {
            int src = sm_src[warp][e];
            float ex = sm_v[warp][e * 8 + hB];
            float4 f = *(const float4*)&g_feat[((size_t)p * NN + src) * HD_ + lane * 4];
            acc.x += ex * f.x; acc.y += ex * f.y; acc.z += ex * f.z; acc.w += ex * f.w;
        }
        __syncwarp();
    }

    float sB = __shfl_sync(0xffffffffu, s, hB);
    float inv = 1.f / sB;
    float zx = acc.x * inv, zy = acc.y * inv, zz = acc.z * inv, zw = acc.w * inv;
    zx = zx > 0.f ? zx : expm1f(zx);
    zy = zy > 0.f ? zy : expm1f(zy);
    zz = zz > 0.f ? zz : expm1f(zz);
    zw = zw > 0.f ? zw : expm1f(zw);
    *(float4*)&g_z[(size_t)t * HD_ + lane * 4] = make_float4(zx, zy, zz, zw);
}

// ---------------- structure attention: w = tanh(z@W1+b1)@w2 (tf32 mma) ----------------
__global__ __launch_bounds__(256) void k_w(
        const float* __restrict__ W1, const float* __restrict__ b1,
        const float* __restrict__ w2) {
    __shared__ unsigned As[128][33];
    __shared__ unsigned Bs[32][132];
    int mpath = blockIdx.y;
    int row0 = blockIdx.x * 128;
    int tid = threadIdx.x;
    int w = tid >> 5, t = tid & 31;
    int mrow = (w & 3) * 32;
    int ncol = (w >> 2) * 64;

    float acc[2][8][4];
#pragma unroll
    for (int nf = 0; nf < 8; nf++) {
        int col = ncol + nf * 8 + (t & 3) * 2;
        float b0 = b1[col], b1v = b1[col + 1];
#pragma unroll
        for (int mf = 0; mf < 2; mf++) {
            acc[mf][nf][0] = b0; acc[mf][nf][1] = b1v;
            acc[mf][nf][2] = b0; acc[mf][nf][3] = b1v;
        }
    }

    for (int kk = 0; kk < HD_; kk += 32) {
#pragma unroll
        for (int j = 0; j < 4; j++) {
            int idx = tid + 256 * j;
            int r = idx >> 3;
            int c = (idx & 7) * 4;
            float4 v = make_float4(0.f, 0.f, 0.f, 0.f);
            if (row0 + r < NN)
                v = *(const float4*)&g_z[((size_t)mpath * NN + row0 + r) * HD_ + kk + c];
            As[r][c] = cvt_tf32(v.x); As[r][c + 1] = cvt_tf32(v.y);
            As[r][c + 2] = cvt_tf32(v.z); As[r][c + 3] = cvt_tf32(v.w);
        }
#pragma unroll
        for (int j = 0; j < 4; j++) {
            int idx = tid + 256 * j;
            int r = idx >> 5;
            int c = (idx & 31) * 4;
            float4 v = *(const float4*)&W1[(size_t)(kk + r) * HD_ + c];
            Bs[r][c] = cvt_tf32(v.x); Bs[r][c + 1] = cvt_tf32(v.y);
            Bs[r][c + 2] = cvt_tf32(v.z); Bs[r][c + 3] = cvt_tf32(v.w);
        }
        __syncthreads();
#pragma unroll
        for (int ks = 0; ks < 32; ks += 8) {
            unsigned a[2][4];
#pragma unroll
            for (int mf = 0; mf < 2; mf++) {
                int r = mrow + mf * 16 + (t >> 2);
                int kc = ks + (t & 3);
                a[mf][0] = As[r][kc];
                a[mf][1] = As[r + 8][kc];
                a[mf][2] = As[r][kc + 4];
                a[mf][3] = As[r + 8][kc + 4];
            }
#pragma unroll
            for (int nf = 0; nf < 8; nf++) {
                int col = ncol + nf * 8 + (t >> 2);
                int kc = ks + (t & 3);
                unsigned b0 = Bs[kc][col];
                unsigned b1f = Bs[kc + 4][col];
                mma_tf32(acc[0][nf], a[0], b0, b1f);
                mma_tf32(acc[1][nf], a[1], b0, b1f);
            }
        }
        __syncthreads();
    }

#pragma unroll
    for (int mf = 0; mf < 2; mf++) {
        int ra = row0 + mrow + mf * 16 + (t >> 2);
        int rb = ra + 8;
        float tA = 0.f, tB = 0.f;
#pragma unroll
        for (int nf = 0; nf < 8; nf++) {
            int col = ncol + nf * 8 + (t & 3) * 2;
            float w0 = w2[col], w1v = w2[col + 1];
            tA += tanh_fast(acc[mf][nf][0]) * w0 + tanh_fast(acc[mf][nf][1]) * w1v;
            tB += tanh_fast(acc[mf][nf][2]) * w0 + tanh_fast(acc[mf][nf][3]) * w1v;
        }
        tA += __shfl_xor_sync(0xffffffffu, tA, 1);
        tA += __shfl_xor_sync(0xffffffffu, tA, 2);
        tB += __shfl_xor_sync(0xffffffffu, tB, 1);
        tB += __shfl_xor_sync(0xffffffffu, tB, 2);
        if ((t & 3) == 0) {
            if (ra < NN) atomicAdd(&g_w[(size_t)mpath * NN + ra], tA);
            if (rb < NN) atomicAdd(&g_w[(size_t)mpath * NN + rb], tB);
        }
    }
}

// ---------------- node softmax weighted sum (vectorized) ----------------
#define NPB 64
__global__ __launch_bounds__(128) void k_beta() {
    __shared__ float4 sred[4][MM][32];
    int lane = threadIdx.x & 31, w = threadIdx.x >> 5;
    int n0 = blockIdx.x * NPB;
    int n1 = n0 + NPB; if (n1 > NN) n1 = NN;
    float4 acc[MM];
    float wsl[MM];
#pragma unroll
    for (int m = 0; m < MM; m++) {
        acc[m] = make_float4(0.f, 0.f, 0.f, 0.f);
        wsl[m] = 0.f;
    }
    for (int n = n0 + w; n < n1; n += 4) {
#pragma unroll
        for (int m = 0; m < MM; m++) {
            float pv = __expf(g_w[(size_t)m * NN + n]);
            float4 zv = *(const float4*)&g_z[((size_t)m * NN + n) * HD_ + lane * 4];
            acc[m].x += pv * zv.x; acc[m].y += pv * zv.y;
            acc[m].z += pv * zv.z; acc[m].w += pv * zv.w;
            wsl[m] += pv;
        }
    }
#pragma unroll
    for (int m = 0; m < MM; m++) {
        sred[w][m][lane] = acc[m];
        if (lane == 0) atomicAdd(&g_wsum[m], wsl[m]);
    }
    __syncthreads();
    if (w == 0) {
#pragma unroll
        for (int m = 0; m < MM; m++) {
            float4 a0 = sred[0][m][lane], a1 = sred[1][m][lane];
            float4 a2 = sred[2][m][lane], a3 = sred[3][m][lane];
            float4 tt = make_float4(a0.x + a1.x + a2.x + a3.x,
                                    a0.y + a1.y + a2.y + a3.y,
                                    a0.z + a1.z + a2.z + a3.z,
                                    a0.w + a1.w + a2.w + a3.w);
            float* o = &g_pz[m * HD_ + lane * 4];
            asm volatile("red.global.add.v4.f32 [%0], {%1,%2,%3,%4};"
                         :: "l"(o), "f"(tt.x), "f"(tt.y), "f"(tt.z), "f"(tt.w)
                         : "memory");
        }
    }
}

__global__ void k_final(const float* __restrict__ pred_w, const float* __restrict__ pred_b,
                        float* __restrict__ out) {
    int t = threadIdx.x;
    if (t < MM * OUT_) {
        int m = t / OUT_, o = t - m * OUT_;
        float inv = 1.f / g_wsum[m];
        float s = pred_b[o];
#pragma unroll 8
        for (int j = 0; j < HD_; j++)
            s += g_pz[m * HD_ + j] * inv * pred_w[(size_t)j * OUT_ + o];
        out[t] = s;
    }
}

// ---------------- launch ----------------
extern "C" void kernel_launch(void* const* d_in, const int* in_sizes, int n_in,
                              void* d_out, int out_size) {
    const float* h      = (const float*)d_in[0];
    const int*   edges  = (const int*)d_in[1];
    const float* fc_w   = (const float*)d_in[2];
    const float* attn_l = (const float*)d_in[3];
    const float* attn_r = (const float*)d_in[4];
    const float* sa_w1  = (const float*)d_in[5];
    const float* sa_b1  = (const float*)d_in[6];
    const float* sa_w2  = (const float*)d_in[7];
    const float* pred_w = (const float*)d_in[8];
    const float* pred_b = (const float*)d_in[9];
    float* out = (float*)d_out;

    void *pdeg, *pcur, *poff, *pwsum, *ppz, *pw;
    cudaGetSymbolAddress(&pdeg, g_deg);
    cudaGetSymbolAddress(&pcur, g_cur);
    cudaGetSymbolAddress(&poff, g_off);
    cudaGetSymbolAddress(&pwsum, g_wsum);
    cudaGetSymbolAddress(&ppz, g_pz);
    cudaGetSymbolAddress(&pw, g_w);
    cudaMemsetAsync(pdeg, 0, sizeof(int) * NTASK);
    cudaMemsetAsync(pwsum, 0, sizeof(float) * MM);
    cudaMemsetAsync(ppz, 0, sizeof(float) * MM * HD_);
    cudaMemsetAsync(pw, 0, sizeof(float) * MM * NN);

    dim3 gg((NN + 127) / 128, MM);
    k_gemm<<<gg, 256>>>(h, fc_w, attn_l, attn_r);

    int et = MM * EE;
    k_count<<<(et + 255) / 256, 256>>>(edges);
    k_scan<<<1, 1024>>>();
    cudaMemcpyAsync(pcur, poff, sizeof(int) * NTASK, cudaMemcpyDeviceToDevice);
    k_scatter<<<(et + 255) / 256, 256>>>(edges);

    k_agg<<<(NTASK + 7) / 8, 256>>>();

    k_w<<<gg, 256>>>(sa_w1, sa_b1, sa_w2);
    k_beta<<<(NN + NPB - 1) / NPB, 128>>>();
    k_final<<<1, 32>>>(pred_w, pred_b, out);
}

// round 7
// speedup vs baseline: 1.8985x; 1.1870x over previous
#include <cuda_runtime.h>
#include <cuda_bf16.h>
#include <math.h>
#include <limits.h>

#define NN 50000
#define EE 800000
#define MM 3
#define IN_ 256
#define HID_ 16
#define HEADS_ 8
#define HD_ 128
#define OUT_ 8
#define NTASK (MM * NN)
#define CAP 32
#define GEMM_BLKS ((NN + 127) / 128)          // 391
#define GEMM_TOT (GEMM_BLKS * MM)             // 1173
#define COUNT_BLKS ((MM * EE + 255) / 256)    // 9375
#define SCAN_BLKS ((NTASK + 1023) / 1024)     // 147

// ---------------- scratch ----------------
__device__ float g_feat[MM * NN * HD_];
__device__ float g_z[MM * NN * HD_];
__device__ float g_el[MM * NN * HEADS_];
__device__ float g_er[MM * NN * HEADS_];
__device__ int   g_deg[NTASK];
__device__ int   g_off[NTASK];
__device__ int   g_cur[NTASK];
__device__ int   g_csr[MM * EE];
__device__ int   g_bsum[SCAN_BLKS];
__device__ float g_wsum[MM];
__device__ float g_pz[MM * HD_];

__device__ __forceinline__ unsigned cvt_tf32(float x) {
    unsigned r;
    asm("cvt.rna.tf32.f32 %0, %1;" : "=r"(r) : "f"(x));
    return r;
}
__device__ __forceinline__ void mma_tf32(float* c, const unsigned* a,
                                         unsigned b0, unsigned b1) {
    asm("mma.sync.aligned.m16n8k8.row.col.f32.tf32.tf32.f32 "
        "{%0,%1,%2,%3},{%4,%5,%6,%7},{%8,%9},{%0,%1,%2,%3};"
        : "+f"(c[0]), "+f"(c[1]), "+f"(c[2]), "+f"(c[3])
        : "r"(a[0]), "r"(a[1]), "r"(a[2]), "r"(a[3]), "r"(b0), "r"(b1));
}
__device__ __forceinline__ float tanh_fast(float x) {
    x = fminf(fmaxf(x, -15.f), 15.f);
    float e = __expf(2.f * x);
    return __fdividef(e - 1.f, e + 1.f);
}

// ---------------- fused GEMM (tf32 mma, el/er epilogue) + edge count ----------------
__global__ __launch_bounds__(256) void k_gemm_count(
        const float* __restrict__ h, const float* __restrict__ W,
        const float* __restrict__ al, const float* __restrict__ ar,
        const int* __restrict__ edges) {
    __shared__ unsigned As[128][33];
    __shared__ unsigned Bs[32][132];
    int tid = threadIdx.x;

    if (blockIdx.x >= GEMM_TOT) {
        // ---- count path ----
        int idx = (blockIdx.x - GEMM_TOT) * 256 + tid;
        if (idx < MM * EE) {
            int p = idx / EE, e = idx - p * EE;
            int dst = edges[(size_t)p * 2 * EE + EE + e];
            atomicAdd(&g_deg[p * NN + dst], 1);
        }
        return;
    }

    // ---- gemm path ----
    int p = blockIdx.x / GEMM_BLKS;
    int row0 = (blockIdx.x - p * GEMM_BLKS) * 128;
    int w = tid >> 5, t = tid & 31;
    int mrow = (w & 3) * 32;
    int ncol = (w >> 2) * 64;
    const float* Wp = W + (size_t)p * IN_ * HD_;

    float acc[2][8][4];
#pragma unroll
    for (int mf = 0; mf < 2; mf++)
#pragma unroll
        for (int nf = 0; nf < 8; nf++)
#pragma unroll
            for (int k = 0; k < 4; k++) acc[mf][nf][k] = 0.f;

    for (int kk = 0; kk < IN_; kk += 32) {
#pragma unroll
        for (int j = 0; j < 4; j++) {
            int idx = tid + 256 * j;
            int r = idx >> 3;
            int c = (idx & 7) * 4;
            float4 v = make_float4(0.f, 0.f, 0.f, 0.f);
            if (row0 + r < NN)
                v = *(const float4*)&h[(size_t)(row0 + r) * IN_ + kk + c];
            As[r][c] = cvt_tf32(v.x); As[r][c + 1] = cvt_tf32(v.y);
            As[r][c + 2] = cvt_tf32(v.z); As[r][c + 3] = cvt_tf32(v.w);
        }
#pragma unroll
        for (int j = 0; j < 4; j++) {
            int idx = tid + 256 * j;
            int r = idx >> 5;
            int c = (idx & 31) * 4;
            float4 v = *(const float4*)&Wp[(size_t)(kk + r) * HD_ + c];
            Bs[r][c] = cvt_tf32(v.x); Bs[r][c + 1] = cvt_tf32(v.y);
            Bs[r][c + 2] = cvt_tf32(v.z); Bs[r][c + 3] = cvt_tf32(v.w);
        }
        __syncthreads();
#pragma unroll
        for (int ks = 0; ks < 32; ks += 8) {
            unsigned a[2][4];
#pragma unroll
            for (int mf = 0; mf < 2; mf++) {
                int r = mrow + mf * 16 + (t >> 2);
                int kc = ks + (t & 3);
                a[mf][0] = As[r][kc];
                a[mf][1] = As[r + 8][kc];
                a[mf][2] = As[r][kc + 4];
                a[mf][3] = As[r + 8][kc + 4];
            }
#pragma unroll
            for (int nf = 0; nf < 8; nf++) {
                int col = ncol + nf * 8 + (t >> 2);
                int kc = ks + (t & 3);
                unsigned b0 = Bs[kc][col];
                unsigned b1 = Bs[kc + 4][col];
                mma_tf32(acc[0][nf], a[0], b0, b1);
                mma_tf32(acc[1][nf], a[1], b0, b1);
            }
        }
        __syncthreads();
    }

    int headbase = (w >> 2) * 4;
    size_t pn = (size_t)p * NN;
#pragma unroll
    for (int mf = 0; mf < 2; mf++) {
        int ra = row0 + mrow + mf * 16 + (t >> 2);
        int rb = ra + 8;
#pragma unroll
        for (int nf = 0; nf < 8; nf++) {
            int col = ncol + nf * 8 + (t & 3) * 2;
            if (ra < NN)
                *(float2*)&g_feat[(pn + ra) * HD_ + col] =
                    make_float2(acc[mf][nf][0], acc[mf][nf][1]);
            if (rb < NN)
                *(float2*)&g_feat[(pn + rb) * HD_ + col] =
                    make_float2(acc[mf][nf][2], acc[mf][nf][3]);
        }
#pragma unroll
        for (int hh = 0; hh < 4; hh++) {
            float sAl = 0.f, sBl = 0.f, sAr = 0.f, sBr = 0.f;
#pragma unroll
            for (int q = 0; q < 2; q++) {
                int nf = hh * 2 + q;
                int col = ncol + nf * 8 + (t & 3) * 2;
                float al0 = al[(size_t)p * HD_ + col], al1 = al[(size_t)p * HD_ + col + 1];
                float ar0 = ar[(size_t)p * HD_ + col], ar1 = ar[(size_t)p * HD_ + col + 1];
                sAl += acc[mf][nf][0] * al0 + acc[mf][nf][1] * al1;
                sBl += acc[mf][nf][2] * al0 + acc[mf][nf][3] * al1;
                sAr += acc[mf][nf][0] * ar0 + acc[mf][nf][1] * ar1;
                sBr += acc[mf][nf][2] * ar0 + acc[mf][nf][3] * ar1;
            }
            sAl += __shfl_xor_sync(0xffffffffu, sAl, 1);
            sAl += __shfl_xor_sync(0xffffffffu, sAl, 2);
            sBl += __shfl_xor_sync(0xffffffffu, sBl, 1);
            sBl += __shfl_xor_sync(0xffffffffu, sBl, 2);
            sAr += __shfl_xor_sync(0xffffffffu, sAr, 1);
            sAr += __shfl_xor_sync(0xffffffffu, sAr, 2);
            sBr += __shfl_xor_sync(0xffffffffu, sBr, 1);
            sBr += __shfl_xor_sync(0xffffffffu, sBr, 2);
            if ((t & 3) == 0) {
                if (ra < NN) {
                    g_el[(pn + ra) * HEADS_ + headbase + hh] = sAl;
                    g_er[(pn + ra) * HEADS_ + headbase + hh] = sAr;
                }
                if (rb < NN) {
                    g_el[(pn + rb) * HEADS_ + headbase + hh] = sBl;
                    g_er[(pn + rb) * HEADS_ + headbase + hh] = sBr;
                }
            }
        }
    }
}

// ---------------- multi-block scan ----------------
__global__ __launch_bounds__(1024) void k_scan1() {
    __shared__ int wsum[32];
    int tid = threadIdx.x, lane = tid & 31, wid = tid >> 5;
    int i = blockIdx.x * 1024 + tid;
    int v = (i < NTASK) ? g_deg[i] : 0;
    int x = v;
#pragma unroll
    for (int off = 1; off < 32; off <<= 1) {
        int y = __shfl_up_sync(0xffffffffu, x, off);
        if (lane >= off) x += y;
    }
    if (lane == 31) wsum[wid] = x;
    __syncthreads();
    if (wid == 0) {
        int s = wsum[lane];
#pragma unroll
        for (int off = 1; off < 32; off <<= 1) {
            int y = __shfl_up_sync(0xffffffffu, s, off);
            if (lane >= off) s += y;
        }
        wsum[lane] = s;
    }
    __syncthreads();
    int prefix = (wid ? wsum[wid - 1] : 0) + x - v;   // exclusive within block
    if (i < NTASK) g_off[i] = prefix;
    if (tid == 0) g_bsum[blockIdx.x] = wsum[31] + 0;  // will be fixed below
    if (tid == 1023) g_bsum[blockIdx.x] = wsum[31];
}

__global__ void k_scan2() {   // 1 block, scan SCAN_BLKS block sums (exclusive)
    __shared__ int s[SCAN_BLKS];
    int tid = threadIdx.x;
    if (tid < SCAN_BLKS) s[tid] = g_bsum[tid];
    __syncthreads();
    // simple serial-ish scan by thread 0 (147 elements, trivial)
    if (tid == 0) {
        int run = 0;
        for (int k = 0; k < SCAN_BLKS; k++) {
            int t = s[k];
            s[k] = run;
            run += t;
        }
    }
    __syncthreads();
    if (tid < SCAN_BLKS) g_bsum[tid] = s[tid];
}

__global__ __launch_bounds__(1024) void k_scan3() {
    int i = blockIdx.x * 1024 + threadIdx.x;
    if (i < NTASK) {
        int o = g_off[i] + g_bsum[blockIdx.x];
        g_off[i] = o;
        g_cur[i] = o;
    }
}

// ---------------- scatter (g_cur pre-set to g_off) ----------------
__global__ void k_scatter(const int* __restrict__ edges) {
    int idx = blockIdx.x * blockDim.x + threadIdx.x;
    if (idx >= MM * EE) return;
    int p = idx / EE, e = idx - p * EE;
    const int* eb = edges + (size_t)p * 2 * EE;
    int src = eb[e], dst = eb[EE + e];
    int pos = atomicAdd(&g_cur[p * NN + dst], 1);
    g_csr[pos] = src;
}

// ---------------- fused edge softmax + aggregation + elu ----------------
__global__ void k_agg() {
    __shared__ float sm_v[8][CAP * 8];
    __shared__ int   sm_src[8][CAP];
    int warp = threadIdx.x >> 5, lane = threadIdx.x & 31;
    int t = blockIdx.x * 8 + warp;
    if (t >= NTASK) return;
    int p = t / NN;
    int deg = g_deg[t];
    int base = g_off[t];

    if (deg == 0) {
        *(float4*)&g_z[(size_t)t * HD_ + lane * 4] = make_float4(0.f, 0.f, 0.f, 0.f);
        return;
    }

    int hA = lane & 7;
    int eSub = lane >> 3;
    int hB = lane >> 2;

    float er_l = 0.f;
    if (lane < 8) er_l = g_er[(size_t)t * HEADS_ + lane];
    float er_hA = __shfl_sync(0xffffffffu, er_l, hA);

    float s = 0.f;
    float4 acc = make_float4(0.f, 0.f, 0.f, 0.f);

    for (int c0 = 0; c0 < deg; c0 += CAP) {
        int cn = min(CAP, deg - c0);
        float cs = 0.f;
        for (int e = eSub; e < cn; e += 4) {
            int src = g_csr[base + c0 + e];
            if (hA == 0) sm_src[warp][e] = src;
            float v = g_el[((size_t)p * NN + src) * HEADS_ + hA] + er_hA;
            v = v > 0.f ? v : 0.2f * v;
            float ex = __expf(v);
            sm_v[warp][e * 8 + hA] = ex;
            cs += ex;
        }
        cs += __shfl_xor_sync(0xffffffffu, cs, 8);
        cs += __shfl_xor_sync(0xffffffffu, cs, 16);
        s += cs;
        __syncwarp();
#pragma unroll 4
        for (int e = 0; e < cn; e++) {
            int src = sm_src[warp][e];
            float ex = sm_v[warp][e * 8 + hB];
            float4 f = *(const float4*)&g_feat[((size_t)p * NN + src) * HD_ + lane * 4];
            acc.x += ex * f.x; acc.y += ex * f.y; acc.z += ex * f.z; acc.w += ex * f.w;
        }
        __syncwarp();
    }

    float sB = __shfl_sync(0xffffffffu, s, hB);
    float inv = 1.f / sB;
    float zx = acc.x * inv, zy = acc.y * inv, zz = acc.z * inv, zw = acc.w * inv;
    zx = zx > 0.f ? zx : expm1f(zx);
    zy = zy > 0.f ? zy : expm1f(zy);
    zz = zz > 0.f ? zz : expm1f(zz);
    zw = zw > 0.f ? zw : expm1f(zw);
    *(float4*)&g_z[(size_t)t * HD_ + lane * 4] = make_float4(zx, zy, zz, zw);
}

// ------- fused structure attention + node-softmax accumulation -------
// w = tanh(z@W1+b1)@w2 per row (block-local), then pv=exp(w), and block
// accumulates pv*z into g_pz + pv into g_wsum directly.
__global__ __launch_bounds__(256) void k_wbeta(
        const float* __restrict__ W1, const float* __restrict__ b1,
        const float* __restrict__ w2) {
    __shared__ unsigned As[128][33];
    __shared__ unsigned Bs[32][132];
    __shared__ float sw[128][2];
    __shared__ float spv[128];
    int mpath = blockIdx.y;
    int row0 = blockIdx.x * 128;
    int tid = threadIdx.x;
    int w = tid >> 5, t = tid & 31;
    int mrow = (w & 3) * 32;
    int ncol = (w >> 2) * 64;
    int half = w >> 2;

    float acc[2][8][4];
#pragma unroll
    for (int nf = 0; nf < 8; nf++) {
        int col = ncol + nf * 8 + (t & 3) * 2;
        float b0 = b1[col], b1v = b1[col + 1];
#pragma unroll
        for (int mf = 0; mf < 2; mf++) {
            acc[mf][nf][0] = b0; acc[mf][nf][1] = b1v;
            acc[mf][nf][2] = b0; acc[mf][nf][3] = b1v;
        }
    }

    for (int kk = 0; kk < HD_; kk += 32) {
#pragma unroll
        for (int j = 0; j < 4; j++) {
            int idx = tid + 256 * j;
            int r = idx >> 3;
            int c = (idx & 7) * 4;
            float4 v = make_float4(0.f, 0.f, 0.f, 0.f);
            if (row0 + r < NN)
                v = *(const float4*)&g_z[((size_t)mpath * NN + row0 + r) * HD_ + kk + c];
            As[r][c] = cvt_tf32(v.x); As[r][c + 1] = cvt_tf32(v.y);
            As[r][c + 2] = cvt_tf32(v.z); As[r][c + 3] = cvt_tf32(v.w);
        }
#pragma unroll
        for (int j = 0; j < 4; j++) {
            int idx = tid + 256 * j;
            int r = idx >> 5;
            int c = (idx & 31) * 4;
            float4 v = *(const float4*)&W1[(size_t)(kk + r) * HD_ + c];
            Bs[r][c] = cvt_tf32(v.x); Bs[r][c + 1] = cvt_tf32(v.y);
            Bs[r][c + 2] = cvt_tf32(v.z); Bs[r][c + 3] = cvt_tf32(v.w);
        }
        __syncthreads();
#pragma unroll
        for (int ks = 0; ks < 32; ks += 8) {
            unsigned a[2][4];
#pragma unroll
            for (int mf = 0; mf < 2; mf++) {
                int r = mrow + mf * 16 + (t >> 2);
                int kc = ks + (t & 3);
                a[mf][0] = As[r][kc];
                a[mf][1] = As[r + 8][kc];
                a[mf][2] = As[r][kc + 4];
                a[mf][3] = As[r + 8][kc + 4];
            }
#pragma unroll
            for (int nf = 0; nf < 8; nf++) {
                int col = ncol + nf * 8 + (t >> 2);
                int kc = ks + (t & 3);
                unsigned b0 = Bs[kc][col];
                unsigned b1f = Bs[kc + 4][col];
                mma_tf32(acc[0][nf], a[0], b0, b1f);
                mma_tf32(acc[1][nf], a[1], b0, b1f);
            }
        }
        __syncthreads();
    }

    // per-row tanh sums over this warp's 64-col half, reduced within quad
#pragma unroll
    for (int mf = 0; mf < 2; mf++) {
        int lra = mrow + mf * 16 + (t >> 2);   // local row
        float tA = 0.f, tB = 0.f;
#pragma unroll
        for (int nf = 0; nf < 8; nf++) {
            int col = ncol + nf * 8 + (t & 3) * 2;
            float w0 = w2[col], w1v = w2[col + 1];
            tA += tanh_fast(acc[mf][nf][0]) * w0 + tanh_fast(acc[mf][nf][1]) * w1v;
            tB += tanh_fast(acc[mf][nf][2]) * w0 + tanh_fast(acc[mf][nf][3]) * w1v;
        }
        tA += __shfl_xor_sync(0xffffffffu, tA, 1);
        tA += __shfl_xor_sync(0xffffffffu, tA, 2);
        tB += __shfl_xor_sync(0xffffffffu, tB, 1);
        tB += __shfl_xor_sync(0xffffffffu, tB, 2);
        if ((t & 3) == 0) {
            sw[lra][half] = tA;
            sw[lra + 8][half] = tB;
        }
    }
    __syncthreads();
    if (tid < 128) {
        float wv = sw[tid][0] + sw[tid][1];
        spv[tid] = (row0 + tid < NN) ? __expf(wv) : 0.f;
    }
    __syncthreads();

    // accumulation: warp w handles local rows [w*16, w*16+16)
    float4 a4 = make_float4(0.f, 0.f, 0.f, 0.f);
    float ws = 0.f;
#pragma unroll
    for (int r = 0; r < 16; r++) {
        int lr = w * 16 + r;
        int gr = row0 + lr;
        float pv = spv[lr];
        if (gr < NN) {
            float4 zv = *(const float4*)&g_z[((size_t)mpath * NN + gr) * HD_ + t * 4];
            a4.x += pv * zv.x; a4.y += pv * zv.y;
            a4.z += pv * zv.z; a4.w += pv * zv.w;
            ws += pv;
        }
    }
    float* o = &g_pz[mpath * HD_ + t * 4];
    asm volatile("red.global.add.v4.f32 [%0], {%1,%2,%3,%4};"
                 :: "l"(o), "f"(a4.x), "f"(a4.y), "f"(a4.z), "f"(a4.w)
                 : "memory");
    if (t == 0) atomicAdd(&g_wsum[mpath], ws);
}

__global__ void k_final(const float* __restrict__ pred_w, const float* __restrict__ pred_b,
                        float* __restrict__ out) {
    int t = threadIdx.x;
    if (t < MM * OUT_) {
        int m = t / OUT_, o = t - m * OUT_;
        float inv = 1.f / g_wsum[m];
        float s = pred_b[o];
#pragma unroll 8
        for (int j = 0; j < HD_; j++)
            s += g_pz[m * HD_ + j] * inv * pred_w[(size_t)j * OUT_ + o];
        out[t] = s;
    }
}

// ---------------- launch ----------------
extern "C" void kernel_launch(void* const* d_in, const int* in_sizes, int n_in,
                              void* d_out, int out_size) {
    const float* h      = (const float*)d_in[0];
    const int*   edges  = (const int*)d_in[1];
    const float* fc_w   = (const float*)d_in[2];
    const float* attn_l = (const float*)d_in[3];
    const float* attn_r = (const float*)d_in[4];
    const float* sa_w1  = (const float*)d_in[5];
    const float* sa_b1  = (const float*)d_in[6];
    const float* sa_w2  = (const float*)d_in[7];
    const float* pred_w = (const float*)d_in[8];
    const float* pred_b = (const float*)d_in[9];
    float* out = (float*)d_out;

    void *pdeg, *pwsum, *ppz;
    cudaGetSymbolAddress(&pdeg, g_deg);
    cudaGetSymbolAddress(&pwsum, g_wsum);
    cudaGetSymbolAddress(&ppz, g_pz);
    cudaMemsetAsync(pdeg, 0, sizeof(int) * NTASK);
    cudaMemsetAsync(pwsum, 0, sizeof(float) * MM);
    cudaMemsetAsync(ppz, 0, sizeof(float) * MM * HD_);

    k_gemm_count<<<GEMM_TOT + COUNT_BLKS, 256>>>(h, fc_w, attn_l, attn_r, edges);

    k_scan1<<<SCAN_BLKS, 1024>>>();
    k_scan2<<<1, 256>>>();
    k_scan3<<<SCAN_BLKS, 1024>>>();

    int et = MM * EE;
    k_scatter<<<(et + 255) / 256, 256>>>(edges);

    k_agg<<<(NTASK + 7) / 8, 256>>>();

    dim3 gw(GEMM_BLKS, MM);
    k_wbeta<<<gw, 256>>>(sa_w1, sa_b1, sa_w2);
    k_final<<<1, 32>>>(pred_w, pred_b, out);
}

// round 8
// speedup vs baseline: 2.0190x; 1.0635x over previous
#include <cuda_runtime.h>
#include <cuda_bf16.h>
#include <math.h>
#include <limits.h>

#define NN 50000
#define EE 800000
#define MM 3
#define IN_ 256
#define HID_ 16
#define HEADS_ 8
#define HD_ 128
#define OUT_ 8
#define NTASK (MM * NN)
#define CAP 32
#define GEMM_BLKS ((NN + 127) / 128)          // 391
#define SCAN_BLKS ((NTASK + 1023) / 1024)     // 147

// ---------------- scratch ----------------
__device__ __nv_bfloat16 g_featb[MM * NN * HD_];
__device__ float g_z[MM * NN * HD_];
__device__ float g_el[MM * NN * HEADS_];
__device__ float g_er[MM * NN * HEADS_];
__device__ int   g_deg[NTASK];
__device__ int   g_off[NTASK];
__device__ int   g_cur[NTASK];
__device__ int   g_csr[MM * EE];
__device__ int   g_bsum[SCAN_BLKS];
__device__ float g_wsum[MM];
__device__ float g_pz[MM * HD_];

__device__ __forceinline__ unsigned cvt_tf32(float x) {
    unsigned r;
    asm("cvt.rna.tf32.f32 %0, %1;" : "=r"(r) : "f"(x));
    return r;
}
__device__ __forceinline__ void mma_tf32(float* c, const unsigned* a,
                                         unsigned b0, unsigned b1) {
    asm("mma.sync.aligned.m16n8k8.row.col.f32.tf32.tf32.f32 "
        "{%0,%1,%2,%3},{%4,%5,%6,%7},{%8,%9},{%0,%1,%2,%3};"
        : "+f"(c[0]), "+f"(c[1]), "+f"(c[2]), "+f"(c[3])
        : "r"(a[0]), "r"(a[1]), "r"(a[2]), "r"(a[3]), "r"(b0), "r"(b1));
}
__device__ __forceinline__ float tanh_fast(float x) {
    x = fminf(fmaxf(x, -15.f), 15.f);
    float e = __expf(2.f * x);
    return __fdividef(e - 1.f, e + 1.f);
}

// ---------------- GEMM: feat(bf16) = h @ fc_w[p] (tf32 mma), fused el/er ----------------
__global__ __launch_bounds__(256) void k_gemm(
        const float* __restrict__ h, const float* __restrict__ W,
        const float* __restrict__ al, const float* __restrict__ ar) {
    __shared__ unsigned As[128][33];
    __shared__ unsigned Bs[32][132];
    int tid = threadIdx.x;
    int p = blockIdx.y;
    int row0 = blockIdx.x * 128;
    int w = tid >> 5, t = tid & 31;
    int mrow = (w & 3) * 32;
    int ncol = (w >> 2) * 64;
    const float* Wp = W + (size_t)p * IN_ * HD_;

    float acc[2][8][4];
#pragma unroll
    for (int mf = 0; mf < 2; mf++)
#pragma unroll
        for (int nf = 0; nf < 8; nf++)
#pragma unroll
            for (int k = 0; k < 4; k++) acc[mf][nf][k] = 0.f;

    for (int kk = 0; kk < IN_; kk += 32) {
#pragma unroll
        for (int j = 0; j < 4; j++) {
            int idx = tid + 256 * j;
            int r = idx >> 3;
            int c = (idx & 7) * 4;
            float4 v = make_float4(0.f, 0.f, 0.f, 0.f);
            if (row0 + r < NN)
                v = *(const float4*)&h[(size_t)(row0 + r) * IN_ + kk + c];
            As[r][c] = cvt_tf32(v.x); As[r][c + 1] = cvt_tf32(v.y);
            As[r][c + 2] = cvt_tf32(v.z); As[r][c + 3] = cvt_tf32(v.w);
        }
#pragma unroll
        for (int j = 0; j < 4; j++) {
            int idx = tid + 256 * j;
            int r = idx >> 5;
            int c = (idx & 31) * 4;
            float4 v = *(const float4*)&Wp[(size_t)(kk + r) * HD_ + c];
            Bs[r][c] = cvt_tf32(v.x); Bs[r][c + 1] = cvt_tf32(v.y);
            Bs[r][c + 2] = cvt_tf32(v.z); Bs[r][c + 3] = cvt_tf32(v.w);
        }
        __syncthreads();
#pragma unroll
        for (int ks = 0; ks < 32; ks += 8) {
            unsigned a[2][4];
#pragma unroll
            for (int mf = 0; mf < 2; mf++) {
                int r = mrow + mf * 16 + (t >> 2);
                int kc = ks + (t & 3);
                a[mf][0] = As[r][kc];
                a[mf][1] = As[r + 8][kc];
                a[mf][2] = As[r][kc + 4];
                a[mf][3] = As[r + 8][kc + 4];
            }
#pragma unroll
            for (int nf = 0; nf < 8; nf++) {
                int col = ncol + nf * 8 + (t >> 2);
                int kc = ks + (t & 3);
                unsigned b0 = Bs[kc][col];
                unsigned b1 = Bs[kc + 4][col];
                mma_tf32(acc[0][nf], a[0], b0, b1);
                mma_tf32(acc[1][nf], a[1], b0, b1);
            }
        }
        __syncthreads();
    }

    int headbase = (w >> 2) * 4;
    size_t pn = (size_t)p * NN;
#pragma unroll
    for (int mf = 0; mf < 2; mf++) {
        int ra = row0 + mrow + mf * 16 + (t >> 2);
        int rb = ra + 8;
#pragma unroll
        for (int nf = 0; nf < 8; nf++) {
            int col = ncol + nf * 8 + (t & 3) * 2;
            if (ra < NN)
                *(__nv_bfloat162*)&g_featb[(pn + ra) * HD_ + col] =
                    __float22bfloat162_rn(make_float2(acc[mf][nf][0], acc[mf][nf][1]));
            if (rb < NN)
                *(__nv_bfloat162*)&g_featb[(pn + rb) * HD_ + col] =
                    __float22bfloat162_rn(make_float2(acc[mf][nf][2], acc[mf][nf][3]));
        }
#pragma unroll
        for (int hh = 0; hh < 4; hh++) {
            float sAl = 0.f, sBl = 0.f, sAr = 0.f, sBr = 0.f;
#pragma unroll
            for (int q = 0; q < 2; q++) {
                int nf = hh * 2 + q;
                int col = ncol + nf * 8 + (t & 3) * 2;
                float al0 = al[(size_t)p * HD_ + col], al1 = al[(size_t)p * HD_ + col + 1];
                float ar0 = ar[(size_t)p * HD_ + col], ar1 = ar[(size_t)p * HD_ + col + 1];
                sAl += acc[mf][nf][0] * al0 + acc[mf][nf][1] * al1;
                sBl += acc[mf][nf][2] * al0 + acc[mf][nf][3] * al1;
                sAr += acc[mf][nf][0] * ar0 + acc[mf][nf][1] * ar1;
                sBr += acc[mf][nf][2] * ar0 + acc[mf][nf][3] * ar1;
            }
            sAl += __shfl_xor_sync(0xffffffffu, sAl, 1);
            sAl += __shfl_xor_sync(0xffffffffu, sAl, 2);
            sBl += __shfl_xor_sync(0xffffffffu, sBl, 1);
            sBl += __shfl_xor_sync(0xffffffffu, sBl, 2);
            sAr += __shfl_xor_sync(0xffffffffu, sAr, 1);
            sAr += __shfl_xor_sync(0xffffffffu, sAr, 2);
            sBr += __shfl_xor_sync(0xffffffffu, sBr, 1);
            sBr += __shfl_xor_sync(0xffffffffu, sBr, 2);
            if ((t & 3) == 0) {
                if (ra < NN) {
                    g_el[(pn + ra) * HEADS_ + headbase + hh] = sAl;
                    g_er[(pn + ra) * HEADS_ + headbase + hh] = sAr;
                }
                if (rb < NN) {
                    g_el[(pn + rb) * HEADS_ + headbase + hh] = sBl;
                    g_er[(pn + rb) * HEADS_ + headbase + hh] = sBr;
                }
            }
        }
    }
}

// ---------------- CSR build ----------------
__global__ void k_count(const int* __restrict__ edges) {
    int idx = blockIdx.x * blockDim.x + threadIdx.x;
    if (idx >= MM * EE) return;
    int p = idx / EE, e = idx - p * EE;
    int dst = edges[(size_t)p * 2 * EE + EE + e];
    atomicAdd(&g_deg[p * NN + dst], 1);
}

__global__ __launch_bounds__(1024) void k_scan1() {
    __shared__ int wsum[32];
    int tid = threadIdx.x, lane = tid & 31, wid = tid >> 5;
    int i = blockIdx.x * 1024 + tid;
    int v = (i < NTASK) ? g_deg[i] : 0;
    int x = v;
#pragma unroll
    for (int off = 1; off < 32; off <<= 1) {
        int y = __shfl_up_sync(0xffffffffu, x, off);
        if (lane >= off) x += y;
    }
    if (lane == 31) wsum[wid] = x;
    __syncthreads();
    if (wid == 0) {
        int s = wsum[lane];
#pragma unroll
        for (int off = 1; off < 32; off <<= 1) {
            int y = __shfl_up_sync(0xffffffffu, s, off);
            if (lane >= off) s += y;
        }
        wsum[lane] = s;
    }
    __syncthreads();
    int prefix = (wid ? wsum[wid - 1] : 0) + x - v;
    if (i < NTASK) g_off[i] = prefix;
    if (tid == 1023) g_bsum[blockIdx.x] = wsum[31];
}

__global__ void k_scan2() {
    __shared__ int s[SCAN_BLKS];
    int tid = threadIdx.x;
    if (tid < SCAN_BLKS) s[tid] = g_bsum[tid];
    __syncthreads();
    if (tid == 0) {
        int run = 0;
        for (int k = 0; k < SCAN_BLKS; k++) {
            int t = s[k];
            s[k] = run;
            run += t;
        }
    }
    __syncthreads();
    if (tid < SCAN_BLKS) g_bsum[tid] = s[tid];
}

__global__ __launch_bounds__(1024) void k_scan3() {
    int i = blockIdx.x * 1024 + threadIdx.x;
    if (i < NTASK) {
        int o = g_off[i] + g_bsum[blockIdx.x];
        g_off[i] = o;
        g_cur[i] = o;
    }
}

__global__ void k_scatter(const int* __restrict__ edges) {
    int idx = blockIdx.x * blockDim.x + threadIdx.x;
    if (idx >= MM * EE) return;
    int p = idx / EE, e = idx - p * EE;
    const int* eb = edges + (size_t)p * 2 * EE;
    int src = eb[e], dst = eb[EE + e];
    int pos = atomicAdd(&g_cur[p * NN + dst], 1);
    g_csr[pos] = src;
}

// ---------------- fused edge softmax + aggregation + elu (bf16 feat gather) ----------------
__global__ void k_agg() {
    __shared__ float sm_v[8][CAP * 8];
    __shared__ int   sm_src[8][CAP];
    int warp = threadIdx.x >> 5, lane = threadIdx.x & 31;
    int t = blockIdx.x * 8 + warp;
    if (t >= NTASK) return;
    int p = t / NN;
    int deg = g_deg[t];
    int base = g_off[t];

    if (deg == 0) {
        *(float4*)&g_z[(size_t)t * HD_ + lane * 4] = make_float4(0.f, 0.f, 0.f, 0.f);
        return;
    }

    int hA = lane & 7;
    int eSub = lane >> 3;
    int hB = lane >> 2;

    float er_l = 0.f;
    if (lane < 8) er_l = g_er[(size_t)t * HEADS_ + lane];
    float er_hA = __shfl_sync(0xffffffffu, er_l, hA);

    float s = 0.f;
    float4 acc = make_float4(0.f, 0.f, 0.f, 0.f);

    for (int c0 = 0; c0 < deg; c0 += CAP) {
        int cn = min(CAP, deg - c0);
        float cs = 0.f;
        for (int e = eSub; e < cn; e += 4) {
            int src = g_csr[base + c0 + e];
            if (hA == 0) sm_src[warp][e] = src;
            float v = g_el[((size_t)p * NN + src) * HEADS_ + hA] + er_hA;
            v = v > 0.f ? v : 0.2f * v;
            float ex = __expf(v);
            sm_v[warp][e * 8 + hA] = ex;
            cs += ex;
        }
        cs += __shfl_xor_sync(0xffffffffu, cs, 8);
        cs += __shfl_xor_sync(0xffffffffu, cs, 16);
        s += cs;
        __syncwarp();
#pragma unroll 4
        for (int e = 0; e < cn; e++) {
            int src = sm_src[warp][e];
            float ex = sm_v[warp][e * 8 + hB];
            uint2 fv = *(const uint2*)&g_featb[((size_t)p * NN + src) * HD_ + lane * 4];
            float2 f0 = __bfloat1622float2(*reinterpret_cast<__nv_bfloat162*>(&fv.x));
            float2 f1 = __bfloat1622float2(*reinterpret_cast<__nv_bfloat162*>(&fv.y));
            acc.x += ex * f0.x; acc.y += ex * f0.y;
            acc.z += ex * f1.x; acc.w += ex * f1.y;
        }
        __syncwarp();
    }

    float sB = __shfl_sync(0xffffffffu, s, hB);
    float inv = 1.f / sB;
    float zx = acc.x * inv, zy = acc.y * inv, zz = acc.z * inv, zw = acc.w * inv;
    zx = zx > 0.f ? zx : expm1f(zx);
    zy = zy > 0.f ? zy : expm1f(zy);
    zz = zz > 0.f ? zz : expm1f(zz);
    zw = zw > 0.f ? zw : expm1f(zw);
    *(float4*)&g_z[(size_t)t * HD_ + lane * 4] = make_float4(zx, zy, zz, zw);
}

// ------- fused structure attention + node-softmax accumulation -------
__global__ __launch_bounds__(256) void k_wbeta(
        const float* __restrict__ W1, const float* __restrict__ b1,
        const float* __restrict__ w2) {
    __shared__ unsigned As[128][33];
    __shared__ unsigned Bs[32][132];
    __shared__ float sw[128][2];
    __shared__ float spv[128];
    int mpath = blockIdx.y;
    int row0 = blockIdx.x * 128;
    int tid = threadIdx.x;
    int w = tid >> 5, t = tid & 31;
    int mrow = (w & 3) * 32;
    int ncol = (w >> 2) * 64;
    int half = w >> 2;

    float acc[2][8][4];
#pragma unroll
    for (int nf = 0; nf < 8; nf++) {
        int col = ncol + nf * 8 + (t & 3) * 2;
        float b0 = b1[col], b1v = b1[col + 1];
#pragma unroll
        for (int mf = 0; mf < 2; mf++) {
            acc[mf][nf][0] = b0; acc[mf][nf][1] = b1v;
            acc[mf][nf][2] = b0; acc[mf][nf][3] = b1v;
        }
    }

    for (int kk = 0; kk < HD_; kk += 32) {
#pragma unroll
        for (int j = 0; j < 4; j++) {
            int idx = tid + 256 * j;
            int r = idx >> 3;
            int c = (idx & 7) * 4;
            float4 v = make_float4(0.f, 0.f, 0.f, 0.f);
            if (row0 + r < NN)
                v = *(const float4*)&g_z[((size_t)mpath * NN + row0 + r) * HD_ + kk + c];
            As[r][c] = cvt_tf32(v.x); As[r][c + 1] = cvt_tf32(v.y);
            As[r][c + 2] = cvt_tf32(v.z); As[r][c + 3] = cvt_tf32(v.w);
        }
#pragma unroll
        for (int j = 0; j < 4; j++) {
            int idx = tid + 256 * j;
            int r = idx >> 5;
            int c = (idx & 31) * 4;
            float4 v = *(const float4*)&W1[(size_t)(kk + r) * HD_ + c];
            Bs[r][c] = cvt_tf32(v.x); Bs[r][c + 1] = cvt_tf32(v.y);
            Bs[r][c + 2] = cvt_tf32(v.z); Bs[r][c + 3] = cvt_tf32(v.w);
        }
        __syncthreads();
#pragma unroll
        for (int ks = 0; ks < 32; ks += 8) {
            unsigned a[2][4];
#pragma unroll
            for (int mf = 0; mf < 2; mf++) {
                int r = mrow + mf * 16 + (t >> 2);
                int kc = ks + (t & 3);
                a[mf][0] = As[r][kc];
                a[mf][1] = As[r + 8][kc];
                a[mf][2] = As[r][kc + 4];
                a[mf][3] = As[r + 8][kc + 4];
            }
#pragma unroll
            for (int nf = 0; nf < 8; nf++) {
                int col = ncol + nf * 8 + (t >> 2);
                int kc = ks + (t & 3);
                unsigned b0 = Bs[kc][col];
                unsigned b1f = Bs[kc + 4][col];
                mma_tf32(acc[0][nf], a[0], b0, b1f);
                mma_tf32(acc[1][nf], a[1], b0, b1f);
            }
        }
        __syncthreads();
    }

#pragma unroll
    for (int mf = 0; mf < 2; mf++) {
        int lra = mrow + mf * 16 + (t >> 2);
        float tA = 0.f, tB = 0.f;
#pragma unroll
        for (int nf = 0; nf < 8; nf++) {
            int col = ncol + nf * 8 + (t & 3) * 2;
            float w0 = w2[col], w1v = w2[col + 1];
            tA += tanh_fast(acc[mf][nf][0]) * w0 + tanh_fast(acc[mf][nf][1]) * w1v;
            tB += tanh_fast(acc[mf][nf][2]) * w0 + tanh_fast(acc[mf][nf][3]) * w1v;
        }
        tA += __shfl_xor_sync(0xffffffffu, tA, 1);
        tA += __shfl_xor_sync(0xffffffffu, tA, 2);
        tB += __shfl_xor_sync(0xffffffffu, tB, 1);
        tB += __shfl_xor_sync(0xffffffffu, tB, 2);
        if ((t & 3) == 0) {
            sw[lra][half] = tA;
            sw[lra + 8][half] = tB;
        }
    }
    __syncthreads();
    if (tid < 128) {
        float wv = sw[tid][0] + sw[tid][1];
        spv[tid] = (row0 + tid < NN) ? __expf(wv) : 0.f;
    }
    __syncthreads();

    float4 a4 = make_float4(0.f, 0.f, 0.f, 0.f);
    float ws = 0.f;
#pragma unroll
    for (int r = 0; r < 16; r++) {
        int lr = w * 16 + r;
        int gr = row0 + lr;
        float pv = spv[lr];
        if (gr < NN) {
            float4 zv = *(const float4*)&g_z[((size_t)mpath * NN + gr) * HD_ + t * 4];
            a4.x += pv * zv.x; a4.y += pv * zv.y;
            a4.z += pv * zv.z; a4.w += pv * zv.w;
            ws += pv;
        }
    }
    float* o = &g_pz[mpath * HD_ + t * 4];
    asm volatile("red.global.add.v4.f32 [%0], {%1,%2,%3,%4};"
                 :: "l"(o), "f"(a4.x), "f"(a4.y), "f"(a4.z), "f"(a4.w)
                 : "memory");
    if (t == 0) atomicAdd(&g_wsum[mpath], ws);
}

__global__ void k_final(const float* __restrict__ pred_w, const float* __restrict__ pred_b,
                        float* __restrict__ out) {
    int t = threadIdx.x;
    if (t < MM * OUT_) {
        int m = t / OUT_, o = t - m * OUT_;
        float inv = 1.f / g_wsum[m];
        float s = pred_b[o];
#pragma unroll 8
        for (int j = 0; j < HD_; j++)
            s += g_pz[m * HD_ + j] * inv * pred_w[(size_t)j * OUT_ + o];
        out[t] = s;
    }
}

// ---------------- launch (forked stream: CSR chain || GEMM) ----------------
extern "C" void kernel_launch(void* const* d_in, const int* in_sizes, int n_in,
                              void* d_out, int out_size) {
    const float* h      = (const float*)d_in[0];
    const int*   edges  = (const int*)d_in[1];
    const float* fc_w   = (const float*)d_in[2];
    const float* attn_l = (const float*)d_in[3];
    const float* attn_r = (const float*)d_in[4];
    const float* sa_w1  = (const float*)d_in[5];
    const float* sa_b1  = (const float*)d_in[6];
    const float* sa_w2  = (const float*)d_in[7];
    const float* pred_w = (const float*)d_in[8];
    const float* pred_b = (const float*)d_in[9];
    float* out = (float*)d_out;

    void *pdeg, *pwsum, *ppz;
    cudaGetSymbolAddress(&pdeg, g_deg);
    cudaGetSymbolAddress(&pwsum, g_wsum);
    cudaGetSymbolAddress(&ppz, g_pz);

    cudaStream_t s2;
    cudaStreamCreateWithFlags(&s2, cudaStreamNonBlocking);
    cudaEvent_t evFork, evJoin;
    cudaEventCreateWithFlags(&evFork, cudaEventDisableTiming);
    cudaEventCreateWithFlags(&evJoin, cudaEventDisableTiming);

    // fork: CSR chain on s2, independent of gemm
    cudaEventRecord(evFork, 0);
    cudaStreamWaitEvent(s2, evFork, 0);

    cudaMemsetAsync(pdeg, 0, sizeof(int) * NTASK, s2);
    int et = MM * EE;
    k_count<<<(et + 255) / 256, 256, 0, s2>>>(edges);
    k_scan1<<<SCAN_BLKS, 1024, 0, s2>>>();
    k_scan2<<<1, 256, 0, s2>>>();
    k_scan3<<<SCAN_BLKS, 1024, 0, s2>>>();
    k_scatter<<<(et + 255) / 256, 256, 0, s2>>>(edges);
    cudaEventRecord(evJoin, s2);

    // main stream: memsets + gemm
    cudaMemsetAsync(pwsum, 0, sizeof(float) * MM);
    cudaMemsetAsync(ppz, 0, sizeof(float) * MM * HD_);
    dim3 gg(GEMM_BLKS, MM);
    k_gemm<<<gg, 256>>>(h, fc_w, attn_l, attn_r);

    // join, then dependent tail
    cudaStreamWaitEvent(0, evJoin, 0);
    k_agg<<<(NTASK + 7) / 8, 256>>>();
    k_wbeta<<<gg, 256>>>(sa_w1, sa_b1, sa_w2);
    k_final<<<1, 32>>>(pred_w, pred_b, out);

    cudaEventDestroy(evFork);
    cudaEventDestroy(evJoin);
    cudaStreamDestroy(s2);
}